// round 8
// baseline (speedup 1.0000x reference)
#include <cuda_runtime.h>
#include <math.h>

#define N 2048
#define D 768
#define SCALE 0.036084391824351615f  /* 1/sqrt(768) */

#define NB 32
#define NT 512
#define NWARP (NT/32)     /* 16 */
#define RPB (D / NB)      /* 24 rows per block */
#define GWTOT (NB*NWARP)  /* 512 global warps */
#define KMAX (N / GWTOT)  /* 4 strided iterations */
#define NSL 3             /* triple-buffered accumulators */

/* k_main dynamic smem layout (float slots) */
#define OFF_WV2   0
#define OFF_Y1    (RPB*D)
#define OFF_Y2    (RPB*D + D)
#define OFF_VT    (RPB*D + 2*D)
#define OFF_Z2    (RPB*D + 3*D)
#define OFF_TMPI  (RPB*D + 4*D)
#define SMEM_FLOATS (RPB*D + 4*D + N)
#define SMEM_BYTES  (SMEM_FLOATS * 4)

// ---------------- device globals ----------------
__device__ float g_K1[N*D];
__device__ float g_V1[N*D];
__device__ float g_D1[N*D];            // scale*(U@WD^T + bD)
__device__ float g_Q2[N*D];
__device__ float g_Z2[N*D];            // scale*(Q2@Wk2)
__device__ float g_KM[N*D];            // K1 @ M
__device__ float g_ZW[N*D];            // Z2 @ Wv2
__device__ float g_KMW[N*D];           // KM @ Wv2
__device__ float g_S1b[(size_t)N*N];   // D1 @ K1^T
__device__ float g_M [D*D];            // scale*(Wq1 @ W_intra[:, :D])
__device__ float g_WD[D*D];
__device__ float g_WQ[D*D];
__device__ float g_W2V[D*D];           // Wk2 @ Wv2
__device__ float g_MW[D*D];            // M @ Wv2
__device__ float g_bD[D];
__device__ float g_bQ[D];
__device__ float g_vacc1[NSL][D];
__device__ float g_vaccV[NSL][D];
__device__ float g_sum1[NSL];
__device__ float g_sum2[NSL];
__device__ float g_phi[NSL];
__device__ int   g_tmp[N];
__device__ unsigned long long g_root;

// ---------------- helpers ----------------
__device__ __forceinline__ float wreduce(float a) {
    #pragma unroll
    for (int o = 16; o; o >>= 1) a += __shfl_xor_sync(0xffffffffu, a, o);
    return a;
}

// warp dot over D=768 (192 float4 = 32 lanes x 6)
__device__ __forceinline__ float wdot(const float* __restrict__ a,
                                      const float* __restrict__ b, int lane) {
    const float4* A = (const float4*)a;
    const float4* B = (const float4*)b;
    float s = 0.f;
    #pragma unroll
    for (int u = 0; u < 6; u++) {
        float4 x = A[lane + 32*u], y = B[lane + 32*u];
        s += x.x*y.x + x.y*y.y + x.z*y.z + x.w*y.w;
    }
    return s;
}

// fence-free grid barrier: release-arrive + acquire-poll on one counter.
// No gpu-scope fence => no CCTL.IVALL => L1D stays warm across steps.
__device__ __forceinline__ void grid_bar(unsigned long long& nbar) {
    __syncthreads();
    if (threadIdx.x == 0) {
        unsigned long long one = 1ULL;
        asm volatile("red.release.gpu.add.u64 [%0], %1;"
                     :: "l"(&g_root), "l"(one) : "memory");
        const unsigned long long tgt = (nbar + 1) * (unsigned long long)NB;
        unsigned long long v;
        do {
            asm volatile("ld.acquire.gpu.u64 %0, [%1];"
                         : "=l"(v) : "l"(&g_root) : "memory");
        } while (v < tgt);
    }
    nbar++;
    __syncthreads();
}

// ================= GEMM tile bodies =================
#define GBM 64
#define GBN 64
#define GBK 16

__device__ __forceinline__ void gemm_ab_body(const float* __restrict__ A,
                                             const float* __restrict__ B,
                                             int ldb, int boff,
                                             float* __restrict__ C,
                                             int m0, int n0, float alpha) {
    __shared__ float As[GBM][GBK + 1];
    __shared__ float Bs[GBK][GBN];
    const int t = threadIdx.x;
    const int tx = t & 15, ty = t >> 4;
    float acc[4][4] = {};
    for (int k0 = 0; k0 < D; k0 += GBK) {
        for (int x = t; x < GBM*GBK; x += 256) {
            int m = x >> 4, k = x & 15;
            As[m][k] = A[(size_t)(m0 + m)*D + k0 + k];
        }
        for (int x = t; x < GBK*GBN; x += 256) {
            int k = x >> 6, n = x & 63;
            Bs[k][n] = B[(size_t)(k0 + k)*ldb + boff + n0 + n];
        }
        __syncthreads();
        #pragma unroll
        for (int kk = 0; kk < GBK; kk++) {
            float a[4], w[4];
            #pragma unroll
            for (int u = 0; u < 4; u++) a[u] = As[ty*4 + u][kk];
            #pragma unroll
            for (int v = 0; v < 4; v++) w[v] = Bs[kk][tx*4 + v];
            #pragma unroll
            for (int u = 0; u < 4; u++)
                #pragma unroll
                for (int v = 0; v < 4; v++) acc[u][v] += a[u] * w[v];
        }
        __syncthreads();
    }
    #pragma unroll
    for (int u = 0; u < 4; u++)
        #pragma unroll
        for (int v = 0; v < 4; v++)
            C[(size_t)(m0 + ty*4 + u)*D + n0 + tx*4 + v] = alpha * acc[u][v];
}

__device__ __forceinline__ void gemm_nt_body(const float* __restrict__ A,
                                             const float* __restrict__ W,
                                             const float* __restrict__ bias,
                                             float* __restrict__ C, int ldc,
                                             int m0, int n0, float alpha) {
    __shared__ float As[GBM][GBK + 1];
    __shared__ float Ws[GBN][GBK + 1];
    const int t = threadIdx.x;
    const int tx = t & 15, ty = t >> 4;
    float acc[4][4] = {};
    for (int k0 = 0; k0 < D; k0 += GBK) {
        for (int x = t; x < GBM*GBK; x += 256) {
            int m = x >> 4, k = x & 15;
            As[m][k] = A[(size_t)(m0 + m)*D + k0 + k];
        }
        for (int x = t; x < GBN*GBK; x += 256) {
            int n = x >> 4, k = x & 15;
            Ws[n][k] = W[(size_t)(n0 + n)*D + k0 + k];
        }
        __syncthreads();
        #pragma unroll
        for (int kk = 0; kk < GBK; kk++) {
            float a[4], w[4];
            #pragma unroll
            for (int u = 0; u < 4; u++) a[u] = As[ty*4 + u][kk];
            #pragma unroll
            for (int v = 0; v < 4; v++) w[v] = Ws[tx*4 + v][kk];
            #pragma unroll
            for (int u = 0; u < 4; u++)
                #pragma unroll
                for (int v = 0; v < 4; v++) acc[u][v] += a[u] * w[v];
        }
        __syncthreads();
    }
    #pragma unroll
    for (int u = 0; u < 4; u++)
        #pragma unroll
        for (int v = 0; v < 4; v++) {
            int m = m0 + ty*4 + u, n = n0 + tx*4 + v;
            float bb = bias ? bias[n] : 0.f;
            C[(size_t)m*ldc + n] = alpha * (acc[u][v] + bb);
        }
}

// ================= pre1: DD GEMMs {M, WD, WQ, W2V} + setup =================
__global__ void __launch_bounds__(256)
k_pre1(const int* __restrict__ spk,
       const float* __restrict__ Wq1, const float* __restrict__ bq1,
       const float* __restrict__ b_intra,
       const float* __restrict__ Wq2, const float* __restrict__ bq2,
       const float* __restrict__ b_inter,
       const float* __restrict__ W_intra, const float* __restrict__ W_inter,
       const float* __restrict__ Wk2, const float* __restrict__ Wv2) {
    const int blk = blockIdx.x, t = threadIdx.x;
    if (blk < 576) {
        const int z = blk / 144, id = blk % 144;
        const int m0 = (id / 12) * GBM, n0 = (id % 12) * GBN;
        switch (z) {
            case 0: gemm_ab_body(Wq1, W_intra, 2*D, 0, g_M,  m0, n0, SCALE); break;
            case 1: gemm_ab_body(Wq1, W_intra, 2*D, D, g_WD, m0, n0, 1.f);   break;
            case 2: gemm_ab_body(Wq2, W_inter, D,   0, g_WQ, m0, n0, 1.f);   break;
            default: gemm_ab_body(Wk2, Wv2,    D,   0, g_W2V, m0, n0, 1.f);  break;
        }
    } else {
        const int sb = blk - 576;
        if (sb < 8) {
            int i = sb * 256 + t;
            int s = spk[i], r = -1;
            for (int j = i - 1; j >= 0; j--)
                if (spk[j] == s) { r = j; break; }
            g_tmp[i] = r;
        } else if (sb < 200) {
            const int rid = (sb - 8) * 8 + (t >> 5);   // 0..1535
            const int lane = t & 31;
            const int mat = rid >= D;
            const int r = mat ? rid - D : rid;
            const float* W  = mat ? Wq2 : Wq1;
            const float* bv = mat ? b_inter : b_intra;
            float a = 0.f;
            for (int k = lane; k < D; k += 32) a += W[(size_t)r*D + k] * bv[k];
            a = wreduce(a);
            if (lane == 0) {
                if (mat) g_bQ[r] = a + bq2[r];
                else     g_bD[r] = a + bq1[r];
            }
        } else {
            if (t == 0) {
                g_root = 0ULL;
                for (int s = 0; s < NSL; s++) {
                    g_sum1[s] = 0.f; g_sum2[s] = 0.f; g_phi[s] = 0.f;
                }
            }
            for (int c = t; c < D; c += 256)
                for (int s = 0; s < NSL; s++) {
                    g_vacc1[s][c] = 0.f; g_vaccV[s][c] = 0.f;
                }
        }
    }
}

// ================= pre2: ND GEMMs {K1, V1, D1, Q2} + MW =================
__global__ void __launch_bounds__(256)
k_pre2(const float* __restrict__ U,
       const float* __restrict__ Wk1, const float* __restrict__ bk1,
       const float* __restrict__ Wv1, const float* __restrict__ bv1,
       const float* __restrict__ Wv2) {
    const int blk = blockIdx.x;
    if (blk < 1536) {
        const int z = blk / 384, id = blk % 384;
        const int m0 = (id / 12) * GBM, n0 = (id % 12) * GBN;
        switch (z) {
            case 0: gemm_nt_body(U, Wk1,  bk1,  g_K1, D, m0, n0, 1.f);   break;
            case 1: gemm_nt_body(U, Wv1,  bv1,  g_V1, D, m0, n0, 1.f);   break;
            case 2: gemm_nt_body(U, g_WD, g_bD, g_D1, D, m0, n0, SCALE); break;
            default: gemm_nt_body(U, g_WQ, g_bQ, g_Q2, D, m0, n0, 1.f);  break;
        }
    } else {
        const int id = blk - 1536;   // 0..143 : MW = M @ Wv2
        const int m0 = (id / 12) * GBM, n0 = (id % 12) * GBN;
        gemm_ab_body(g_M, Wv2, D, 0, g_MW, m0, n0, 1.f);
    }
}

// ================= pre3: post GEMMs {Z2, KM, ZW, KMW} + S1b (lower tri) =================
__global__ void __launch_bounds__(256)
k_pre3(const float* __restrict__ Wk2) {
    const int blk = blockIdx.x;
    if (blk < 1536) {
        const int z = blk / 384, id = blk % 384;
        const int m0 = (id / 12) * GBM, n0 = (id % 12) * GBN;
        switch (z) {
            case 0: gemm_ab_body(g_Q2, Wk2,   D, 0, g_Z2,  m0, n0, SCALE); break;
            case 1: gemm_ab_body(g_K1, g_M,   D, 0, g_KM,  m0, n0, 1.f);   break;
            case 2: gemm_ab_body(g_Q2, g_W2V, D, 0, g_ZW,  m0, n0, SCALE); break;
            default: gemm_ab_body(g_K1, g_MW, D, 0, g_KMW, m0, n0, 1.f);   break;
        }
    } else {
        const int id = blk - 1536;   // 0..1023 : S1b = D1 @ K1^T (N x N)
        const int bm = id / 32, bn = id % 32;
        if (bn > bm) return;         // only j <= i needed
        gemm_nt_body(g_D1, g_K1, (const float*)0, g_S1b, N, bm*GBM, bn*GBN, 1.f);
    }
}

// ================= main recurrence: 32 CTAs, ONE fence-free barrier/step =================
__global__ void __launch_bounds__(NT, 1)
k_main(const float* __restrict__ U,
       const float* __restrict__ Wv2, const float* __restrict__ bv2,
       float* __restrict__ Vout) {
    extern __shared__ float sm[];
    float* sWv2  = sm + OFF_WV2;
    float* sY1   = sm + OFF_Y1;
    float* sY2   = sm + OFF_Y2;
    float* sVt   = sm + OFF_VT;
    float* sZ2   = sm + OFF_Z2;
    int*   sTmpI = (int*)(sm + OFF_TMPI);

    __shared__ float sE1[KMAX*NWARP], sE2[KMAX*NWARP];

    const int b = blockIdx.x, t = threadIdx.x;
    const int warp = t >> 5, lane = t & 31;
    const int gw = b * NWARP + warp;   // 0..511

    // one-time: Wv2 rows + tmp[] into SMEM
    for (int x = t; x < RPB*D; x += NT)
        sWv2[x] = Wv2[(size_t)(b*RPB)*D + x];
    for (int x = t; x < N; x += NT) sTmpI[x] = g_tmp[x];
    __syncthreads();

    unsigned long long nbar = 0;

    for (int i = 0; i <= N; i++) {
        const int tmp = (i < N) ? sTmpI[i] : -1;
        const int p = i % 3, q = (i + 2) % 3, z = (i + 1) % 3;
        bool hv = false;
        const bool fresh = (i > 0) && (tmp == i - 1);

        // ---- build y1/y2 (implicit V[i-1] = y1 + Wv2*y2) ----
        if (i > 0) {
            const int tprev = sTmpI[i-1];
            hv = (tprev >= 0);
            if (hv) {
                const float s1i = 1.0f / __ldcg(&g_sum1[q]);
                const float s2i = 1.0f / __ldcg(&g_sum2[q]);
                const float ph  = __ldcg(&g_phi[q]);
                const float* vp2 = Vout + (size_t)(i-2)*D;   // i>=2 when hv
                for (int c = t; c < D; c += NT) {
                    sY1[c] = __ldcg(&g_vacc1[q][c]) * s1i + bv2[c];
                    sY2[c] = (__ldcg(&g_vaccV[q][c]) + ph * vp2[c]) * s2i;
                }
            } else {
                const float* ur = U + (size_t)(i-1)*D;
                for (int c = t; c < D; c += NT) { sY1[c] = ur[c]; sY2[c] = 0.f; }
            }
        }
        if (tmp >= 0) {
            const float* z2r = g_Z2 + (size_t)i*D;
            for (int c = t; c < D; c += NT) sZ2[c] = z2r[c];
            if (!fresh) {
                const float* vt = Vout + (size_t)tmp*D;
                for (int c = t; c < D; c += NT) sVt[c] = vt[c];
            }
        }
        // zero slot z (block-owned columns)
        if (t < RPB) {
            g_vacc1[z][b*RPB + t] = 0.f;
            g_vaccV[z][b*RPB + t] = 0.f;
        }
        if (b == 0 && t == 0) { g_sum1[z] = 0.f; g_sum2[z] = 0.f; g_phi[z] = 0.f; }
        __syncthreads();

        if (tmp >= 0) {
            // S1b prefetch (lane 0 only)
            float s1v[KMAX];
            #pragma unroll
            for (int k = 0; k < KMAX; k++) {
                const int j = k*GWTOT + gw;
                s1v[k] = (lane == 0 && j <= i) ? __ldg(&g_S1b[(size_t)i*N + j]) : 0.f;
            }
            // intra scores: rows j = gw + k*512 (<= i)
            #pragma unroll
            for (int k = 0; k < KMAX; k++) {
                const int j = k*GWTOT + gw;
                float e = 0.f;
                if (j <= i) {
                    float a;
                    if (fresh) {
                        a = wdot(g_KM + (size_t)j*D, sY1, lane);
                        if (hv) a += wdot(g_KMW + (size_t)j*D, sY2, lane);
                    } else {
                        a = wdot(g_KM + (size_t)j*D, sVt, lane);
                    }
                    a = wreduce(a);
                    e = __expf(a + s1v[k]);
                }
                if (lane == 0) sE1[k*NWARP + warp] = e;
            }
            // inter direct scores: rows j = tmp + gw + k*512 (<= i-2)
            #pragma unroll
            for (int k = 0; k < KMAX; k++) {
                const int j = tmp + k*GWTOT + gw;
                float e = 0.f;
                if (j <= i - 2) {
                    float a = wreduce(wdot(Vout + (size_t)j*D, sZ2, lane));
                    e = __expf(a);
                }
                if (lane == 0) sE2[k*NWARP + warp] = e;
            }
            // fresh inter row j = i-1 (deferred via phi); unique warp
            if (gw == ((i - 1 - tmp) & (GWTOT - 1))) {
                float a = wdot(sZ2, sY1, lane);
                if (hv) a += wdot(g_ZW + (size_t)i*D, sY2, lane);
                a = wreduce(a);
                if (lane == 0) {
                    const float e = __expf(a);
                    atomicAdd(&g_sum2[p], e);
                    g_phi[p] = e;
                }
            }
        }
        // ---- finalize V[i-1]: block-owned rows ----
        if (i > 0) {
            for (int rr = warp; rr < RPB; rr += NWARP) {
                const int r = b*RPB + rr;
                float a = 0.f;
                if (hv) a = wreduce(wdot(sWv2 + rr*D, sY2, lane));
                if (lane == 0) Vout[(size_t)(i-1)*D + r] = sY1[r] + a;
            }
        }
        if (i == N) break;
        __syncthreads();

        if (tmp >= 0) {
            // block sums -> global (64 entries each)
            if (warp == 0) {
                float v1 = sE1[lane] + sE1[lane + 32];
                float v2 = sE2[lane] + sE2[lane + 32];
                v1 = wreduce(v1); v2 = wreduce(v2);
                if (lane == 0) {
                    if (v1 != 0.f) atomicAdd(&g_sum1[p], v1);
                    if (v2 != 0.f) atomicAdd(&g_sum2[p], v2);
                }
            }
            // column accumulation: one global atomic per column per block
            for (int c = t; c < D; c += NT) {
                float a1 = 0.f, a2 = 0.f;
                bool h1 = false, h2 = false;
                #pragma unroll
                for (int k = 0; k < KMAX; k++) {
                    const int base1 = k*GWTOT + b*NWARP;
                    int c1 = i + 1 - base1; if (c1 > NWARP) c1 = NWARP;
                    for (int w = 0; w < c1; w++) {
                        a1 += sE1[k*NWARP + w] * g_V1[(size_t)(base1 + w)*D + c];
                        h1 = true;
                    }
                    const int base2 = tmp + k*GWTOT + b*NWARP;
                    int c2 = i - 1 - base2; if (c2 > NWARP) c2 = NWARP;
                    for (int w = 0; w < c2; w++) {
                        a2 += sE2[k*NWARP + w] * Vout[(size_t)(base2 + w)*D + c];
                        h2 = true;
                    }
                }
                if (h1) atomicAdd(&g_vacc1[p][c], a1);
                if (h2) atomicAdd(&g_vaccV[p][c], a2);
            }
        }
        grid_bar(nbar);
    }
}

// ---------------- launch : k_main is launch #4 ----------------
extern "C" void kernel_launch(void* const* d_in, const int* in_sizes, int n_in,
                              void* d_out, int out_size) {
    const float* U       = (const float*)d_in[0];
    const int*   spk     = (const int*)  d_in[1];
    const float* W_intra = (const float*)d_in[2];
    const float* b_intra = (const float*)d_in[3];
    const float* W_inter = (const float*)d_in[4];
    const float* b_inter = (const float*)d_in[5];
    const float* Wq1 = (const float*)d_in[6];  const float* bq1 = (const float*)d_in[7];
    const float* Wk1 = (const float*)d_in[8];  const float* bk1 = (const float*)d_in[9];
    const float* Wv1 = (const float*)d_in[10]; const float* bv1 = (const float*)d_in[11];
    const float* Wq2 = (const float*)d_in[12]; const float* bq2 = (const float*)d_in[13];
    const float* Wk2 = (const float*)d_in[14]; const float* bk2 = (const float*)d_in[15];
    const float* Wv2 = (const float*)d_in[16]; const float* bv2 = (const float*)d_in[17];
    float* Vout = (float*)d_out;
    (void)in_sizes; (void)n_in; (void)out_size; (void)bk2;

    cudaFuncSetAttribute(k_main, cudaFuncAttributeMaxDynamicSharedMemorySize, SMEM_BYTES);

    k_pre1<<<777, 256>>>(spk, Wq1, bq1, b_intra, Wq2, bq2, b_inter,
                         W_intra, W_inter, Wk2, Wv2);                 // 1
    k_pre2<<<1680, 256>>>(U, Wk1, bk1, Wv1, bv1, Wv2);                // 2
    k_pre3<<<2560, 256>>>(Wk2);                                       // 3
    k_main<<<NB, NT, SMEM_BYTES>>>(U, Wv2, bv2, Vout);                // 4
}

// round 9
// speedup vs baseline: 1.3784x; 1.3784x over previous
#include <cuda_runtime.h>
#include <math.h>

#define N 2048
#define D 768
#define SCALE 0.036084391824351615f  /* 1/sqrt(768) */

#define NB 128
#define NT 512
#define NWARP (NT/32)     /* 16 */
#define RPB (D / NB)      /* 6 rows per block */
#define GWTOT (NB*NWARP)  /* 2048 global warps: 1 row per warp */
#define NSL 3             /* triple-buffered accumulators */

/* k_main dynamic smem layout (float slots) */
#define OFF_WV2   0
#define OFF_Y1    (RPB*D)
#define OFF_Y2    (RPB*D + D)
#define OFF_VT    (RPB*D + 2*D)
#define OFF_VTN   (RPB*D + 3*D)
#define OFF_Z2    (RPB*D + 4*D)
#define OFF_Z2N   (RPB*D + 5*D)
#define OFF_TMPI  (RPB*D + 6*D)
#define SMEM_FLOATS (RPB*D + 6*D + N)
#define SMEM_BYTES  (SMEM_FLOATS * 4)

// ---------------- device globals ----------------
__device__ float g_K1[N*D];
__device__ float g_V1[N*D];
__device__ float g_D1[N*D];            // scale*(U@WD^T + bD)
__device__ float g_Q2[N*D];
__device__ float g_Z2[N*D];            // scale*(Q2@Wk2)
__device__ float g_KM[N*D];            // K1 @ M
__device__ float g_ZW[N*D];            // Z2 @ Wv2
__device__ float g_KMW[N*D];           // KM @ Wv2
__device__ float g_S1b[(size_t)N*N];   // D1 @ K1^T (lower tri used)
__device__ float g_M [D*D];            // scale*(Wq1 @ W_intra[:, :D])
__device__ float g_WD[D*D];
__device__ float g_WQ[D*D];
__device__ float g_W2V[D*D];           // Wk2 @ Wv2
__device__ float g_MW[D*D];            // M @ Wv2
__device__ float g_bD[D];
__device__ float g_bQ[D];
__device__ float g_vacc1[NSL][D];
__device__ float g_vaccV[NSL][D];
__device__ float g_sum1[NSL];
__device__ float g_sum2[NSL];
__device__ float g_phi[NSL];
__device__ int   g_tmp[N];
__device__ unsigned long long g_root;

// ---------------- helpers ----------------
__device__ __forceinline__ float wreduce(float a) {
    #pragma unroll
    for (int o = 16; o; o >>= 1) a += __shfl_xor_sync(0xffffffffu, a, o);
    return a;
}

// warp dot over D=768 (192 float4 = 32 lanes x 6)
__device__ __forceinline__ float wdot(const float* __restrict__ a,
                                      const float* __restrict__ b, int lane) {
    const float4* A = (const float4*)a;
    const float4* B = (const float4*)b;
    float s = 0.f;
    #pragma unroll
    for (int u = 0; u < 6; u++) {
        float4 x = A[lane + 32*u], y = B[lane + 32*u];
        s += x.x*y.x + x.y*y.y + x.z*y.z + x.w*y.w;
    }
    return s;
}

// fence-free grid barrier: release-arrive + acquire-poll on one counter.
__device__ __forceinline__ void grid_bar(unsigned long long& nbar) {
    __syncthreads();
    if (threadIdx.x == 0) {
        unsigned long long one = 1ULL;
        asm volatile("red.release.gpu.add.u64 [%0], %1;"
                     :: "l"(&g_root), "l"(one) : "memory");
        const unsigned long long tgt = (nbar + 1) * (unsigned long long)NB;
        unsigned long long v;
        do {
            asm volatile("ld.acquire.gpu.u64 %0, [%1];"
                         : "=l"(v) : "l"(&g_root) : "memory");
        } while (v < tgt);
    }
    nbar++;
    __syncthreads();
}

// ================= GEMM tile bodies =================
#define GBM 64
#define GBN 64
#define GBK 16

__device__ __forceinline__ void gemm_ab_body(const float* __restrict__ A,
                                             const float* __restrict__ B,
                                             int ldb, int boff,
                                             float* __restrict__ C,
                                             int m0, int n0, float alpha) {
    __shared__ float As[GBM][GBK + 1];
    __shared__ float Bs[GBK][GBN];
    const int t = threadIdx.x;
    const int tx = t & 15, ty = t >> 4;
    float acc[4][4] = {};
    for (int k0 = 0; k0 < D; k0 += GBK) {
        for (int x = t; x < GBM*GBK; x += 256) {
            int m = x >> 4, k = x & 15;
            As[m][k] = A[(size_t)(m0 + m)*D + k0 + k];
        }
        for (int x = t; x < GBK*GBN; x += 256) {
            int k = x >> 6, n = x & 63;
            Bs[k][n] = B[(size_t)(k0 + k)*ldb + boff + n0 + n];
        }
        __syncthreads();
        #pragma unroll
        for (int kk = 0; kk < GBK; kk++) {
            float a[4], w[4];
            #pragma unroll
            for (int u = 0; u < 4; u++) a[u] = As[ty*4 + u][kk];
            #pragma unroll
            for (int v = 0; v < 4; v++) w[v] = Bs[kk][tx*4 + v];
            #pragma unroll
            for (int u = 0; u < 4; u++)
                #pragma unroll
                for (int v = 0; v < 4; v++) acc[u][v] += a[u] * w[v];
        }
        __syncthreads();
    }
    #pragma unroll
    for (int u = 0; u < 4; u++)
        #pragma unroll
        for (int v = 0; v < 4; v++)
            C[(size_t)(m0 + ty*4 + u)*D + n0 + tx*4 + v] = alpha * acc[u][v];
}

__device__ __forceinline__ void gemm_nt_body(const float* __restrict__ A,
                                             const float* __restrict__ W,
                                             const float* __restrict__ bias,
                                             float* __restrict__ C, int ldc,
                                             int m0, int n0, float alpha) {
    __shared__ float As[GBM][GBK + 1];
    __shared__ float Ws[GBN][GBK + 1];
    const int t = threadIdx.x;
    const int tx = t & 15, ty = t >> 4;
    float acc[4][4] = {};
    for (int k0 = 0; k0 < D; k0 += GBK) {
        for (int x = t; x < GBM*GBK; x += 256) {
            int m = x >> 4, k = x & 15;
            As[m][k] = A[(size_t)(m0 + m)*D + k0 + k];
        }
        for (int x = t; x < GBN*GBK; x += 256) {
            int n = x >> 4, k = x & 15;
            Ws[n][k] = W[(size_t)(n0 + n)*D + k0 + k];
        }
        __syncthreads();
        #pragma unroll
        for (int kk = 0; kk < GBK; kk++) {
            float a[4], w[4];
            #pragma unroll
            for (int u = 0; u < 4; u++) a[u] = As[ty*4 + u][kk];
            #pragma unroll
            for (int v = 0; v < 4; v++) w[v] = Ws[tx*4 + v][kk];
            #pragma unroll
            for (int u = 0; u < 4; u++)
                #pragma unroll
                for (int v = 0; v < 4; v++) acc[u][v] += a[u] * w[v];
        }
        __syncthreads();
    }
    #pragma unroll
    for (int u = 0; u < 4; u++)
        #pragma unroll
        for (int v = 0; v < 4; v++) {
            int m = m0 + ty*4 + u, n = n0 + tx*4 + v;
            float bb = bias ? bias[n] : 0.f;
            C[(size_t)m*ldc + n] = alpha * (acc[u][v] + bb);
        }
}

// ================= pre1: DD GEMMs {M, WD, WQ, W2V} + setup =================
__global__ void __launch_bounds__(256)
k_pre1(const int* __restrict__ spk,
       const float* __restrict__ Wq1, const float* __restrict__ bq1,
       const float* __restrict__ b_intra,
       const float* __restrict__ Wq2, const float* __restrict__ bq2,
       const float* __restrict__ b_inter,
       const float* __restrict__ W_intra, const float* __restrict__ W_inter,
       const float* __restrict__ Wk2, const float* __restrict__ Wv2) {
    const int blk = blockIdx.x, t = threadIdx.x;
    if (blk < 576) {
        const int z = blk / 144, id = blk % 144;
        const int m0 = (id / 12) * GBM, n0 = (id % 12) * GBN;
        switch (z) {
            case 0: gemm_ab_body(Wq1, W_intra, 2*D, 0, g_M,  m0, n0, SCALE); break;
            case 1: gemm_ab_body(Wq1, W_intra, 2*D, D, g_WD, m0, n0, 1.f);   break;
            case 2: gemm_ab_body(Wq2, W_inter, D,   0, g_WQ, m0, n0, 1.f);   break;
            default: gemm_ab_body(Wk2, Wv2,    D,   0, g_W2V, m0, n0, 1.f);  break;
        }
    } else {
        const int sb = blk - 576;
        if (sb < 8) {
            int i = sb * 256 + t;
            int s = spk[i], r = -1;
            for (int j = i - 1; j >= 0; j--)
                if (spk[j] == s) { r = j; break; }
            g_tmp[i] = r;
        } else if (sb < 200) {
            const int rid = (sb - 8) * 8 + (t >> 5);   // 0..1535
            const int lane = t & 31;
            const int mat = rid >= D;
            const int r = mat ? rid - D : rid;
            const float* W  = mat ? Wq2 : Wq1;
            const float* bv = mat ? b_inter : b_intra;
            float a = 0.f;
            for (int k = lane; k < D; k += 32) a += W[(size_t)r*D + k] * bv[k];
            a = wreduce(a);
            if (lane == 0) {
                if (mat) g_bQ[r] = a + bq2[r];
                else     g_bD[r] = a + bq1[r];
            }
        } else {
            if (t == 0) {
                g_root = 0ULL;
                for (int s = 0; s < NSL; s++) {
                    g_sum1[s] = 0.f; g_sum2[s] = 0.f; g_phi[s] = 0.f;
                }
            }
            for (int c = t; c < D; c += 256)
                for (int s = 0; s < NSL; s++) {
                    g_vacc1[s][c] = 0.f; g_vaccV[s][c] = 0.f;
                }
        }
    }
}

// ================= pre2: ND GEMMs {K1, V1, D1, Q2} + MW =================
__global__ void __launch_bounds__(256)
k_pre2(const float* __restrict__ U,
       const float* __restrict__ Wk1, const float* __restrict__ bk1,
       const float* __restrict__ Wv1, const float* __restrict__ bv1,
       const float* __restrict__ Wv2) {
    const int blk = blockIdx.x;
    if (blk < 1536) {
        const int z = blk / 384, id = blk % 384;
        const int m0 = (id / 12) * GBM, n0 = (id % 12) * GBN;
        switch (z) {
            case 0: gemm_nt_body(U, Wk1,  bk1,  g_K1, D, m0, n0, 1.f);   break;
            case 1: gemm_nt_body(U, Wv1,  bv1,  g_V1, D, m0, n0, 1.f);   break;
            case 2: gemm_nt_body(U, g_WD, g_bD, g_D1, D, m0, n0, SCALE); break;
            default: gemm_nt_body(U, g_WQ, g_bQ, g_Q2, D, m0, n0, 1.f);  break;
        }
    } else {
        const int id = blk - 1536;   // 0..143 : MW = M @ Wv2
        const int m0 = (id / 12) * GBM, n0 = (id % 12) * GBN;
        gemm_ab_body(g_M, Wv2, D, 0, g_MW, m0, n0, 1.f);
    }
}

// ================= pre3: post GEMMs {Z2, KM, ZW, KMW} + S1b (lower tri) =================
__global__ void __launch_bounds__(256)
k_pre3(const float* __restrict__ Wk2) {
    const int blk = blockIdx.x;
    if (blk < 1536) {
        const int z = blk / 384, id = blk % 384;
        const int m0 = (id / 12) * GBM, n0 = (id % 12) * GBN;
        switch (z) {
            case 0: gemm_ab_body(g_Q2, Wk2,   D, 0, g_Z2,  m0, n0, SCALE); break;
            case 1: gemm_ab_body(g_K1, g_M,   D, 0, g_KM,  m0, n0, 1.f);   break;
            case 2: gemm_ab_body(g_Q2, g_W2V, D, 0, g_ZW,  m0, n0, SCALE); break;
            default: gemm_ab_body(g_K1, g_MW, D, 0, g_KMW, m0, n0, 1.f);   break;
        }
    } else {
        const int id = blk - 1536;   // 0..1023 : S1b = D1 @ K1^T (N x N)
        const int bm = id / 32, bn = id % 32;
        if (bn > bm) return;         // only j <= i needed
        gemm_nt_body(g_D1, g_K1, (const float*)0, g_S1b, N, bm*GBM, bn*GBN, 1.f);
    }
}

// ================= main recurrence: pipelined, ONE barrier/step =================
__global__ void __launch_bounds__(NT, 1)
k_main(const float* __restrict__ U,
       const float* __restrict__ Wv2, const float* __restrict__ bv2,
       float* __restrict__ Vout) {
    extern __shared__ float sm[];
    float* sWv2  = sm + OFF_WV2;
    float* sY1   = sm + OFF_Y1;
    float* sY2   = sm + OFF_Y2;
    float* sVt   = sm + OFF_VT;
    float* sVtN  = sm + OFF_VTN;
    float* sZ2   = sm + OFF_Z2;
    float* sZ2N  = sm + OFF_Z2N;
    int*   sTmpI = (int*)(sm + OFF_TMPI);

    __shared__ float sE1[2][NWARP], sE2[2][NWARP];

    const int b = blockIdx.x, t = threadIdx.x;
    const int warp = t >> 5, lane = t & 31;
    const int gw = b * NWARP + warp;   // global warp = global row index

    for (int x = t; x < RPB*D; x += NT)
        sWv2[x] = Wv2[(size_t)(b*RPB)*D + x];
    for (int x = t; x < N; x += NT) sTmpI[x] = g_tmp[x];
    __syncthreads();

    unsigned long long nbar = 0;

    for (int i = 0; i <= N; i++) {
        const int tmp  = (i < N)     ? sTmpI[i]     : -1;
        const int tmpn = (i + 1 < N) ? sTmpI[i + 1] : -1;
        const int p = i % 3, q = (i + 2) % 3, z = (i + 1) % 3;
        const int par = i & 1, parn = par ^ 1;
        bool hv = false;
        const bool fresh = (tmp >= 0) && (tmp == i - 1);
        const bool semi  = (tmp >= 0) && (tmp == i - 2);
        const bool pre   = (tmp >= 0) && (tmp <= i - 3);
        const bool preN  = (i + 1 < N) && (tmpn >= 0) && (tmpn <= i - 2);

        // ---- phase head: y-build + smem loads ----
        if (i > 0) {
            hv = (sTmpI[i-1] >= 0);
            if (hv) {
                float sv1 = 0.f, sv2 = 0.f, pv = 0.f;
                if (lane == 0) {
                    sv1 = __ldcg(&g_sum1[q]);
                    sv2 = __ldcg(&g_sum2[q]);
                    pv  = __ldcg(&g_phi[q]);
                }
                sv1 = __shfl_sync(0xffffffffu, sv1, 0);
                sv2 = __shfl_sync(0xffffffffu, sv2, 0);
                pv  = __shfl_sync(0xffffffffu, pv, 0);
                const float s1i = 1.0f / sv1, s2i = 1.0f / sv2;
                const float* vp2 = Vout + (size_t)(i-2)*D;   // i>=2 when hv
                for (int c = t; c < D; c += NT) {
                    sY1[c] = __ldcg(&g_vacc1[q][c]) * s1i + bv2[c];
                    sY2[c] = (__ldcg(&g_vaccV[q][c]) + pv * vp2[c]) * s2i;
                }
            } else {
                const float* ur = U + (size_t)(i-1)*D;
                for (int c = t; c < D; c += NT) { sY1[c] = ur[c]; sY2[c] = 0.f; }
            }
        }
        if (tmp >= 0) {
            const float* z2r = g_Z2 + (size_t)i*D;
            for (int c = t; c < D; c += NT) sZ2[c] = z2r[c];
            if (semi) {
                const float* vt = Vout + (size_t)tmp*D;      // row i-2: ready
                for (int c = t; c < D; c += NT) sVt[c] = vt[c];
            }
        }
        if (preN) {
            const float* vtn = Vout + (size_t)tmpn*D;        // row <= i-2: ready
            const float* z2n = g_Z2 + (size_t)(i+1)*D;
            for (int c = t; c < D; c += NT) { sVtN[c] = vtn[c]; sZ2N[c] = z2n[c]; }
        }
        if (t < RPB) {
            g_vacc1[z][b*RPB + t] = 0.f;
            g_vaccV[z][b*RPB + t] = 0.f;
        }
        if (b == 0 && t == 0) { g_sum1[z] = 0.f; g_sum2[z] = 0.f; g_phi[z] = 0.f; }
        __syncthreads();

        float* E1  = sE1[par];  float* E2  = sE2[par];
        float* E1n = sE1[parn]; float* E2n = sE2[parn];

        // ---- complete scores for step i ----
        if (tmp >= 0) {
            if (fresh) {
                // intra via implicit V[i-1] = y1 + Wv2*y2
                float s1v = (lane == 0 && gw <= i) ? __ldg(&g_S1b[(size_t)i*N + gw]) : 0.f;
                float e = 0.f;
                if (gw <= i) {
                    float a = wdot(g_KM + (size_t)gw*D, sY1, lane);
                    if (hv) a += wdot(g_KMW + (size_t)gw*D, sY2, lane);
                    a = wreduce(a);
                    e = __expf(a + s1v);
                }
                if (lane == 0) { E1[warp] = e; E2[warp] = 0.f; }   // window = {i-1} (phi)
            } else if (semi) {
                float s1v = (lane == 0 && gw <= i) ? __ldg(&g_S1b[(size_t)i*N + gw]) : 0.f;
                float e = 0.f;
                if (gw <= i) {
                    float a = wreduce(wdot(g_KM + (size_t)gw*D, sVt, lane));
                    e = __expf(a + s1v);
                }
                float e2 = 0.f;
                if (gw == 0) {   // inter direct row j = tmp = i-2
                    float a = wreduce(wdot(Vout + (size_t)(i-2)*D, sZ2, lane));
                    e2 = __expf(a);
                }
                if (lane == 0) { E1[warp] = e; E2[warp] = e2; }
            } else if (pre) {
                // E1/E2 precomputed last phase; add inter row j = i-2 now
                if (gw == i - 2 - tmp) {
                    float a = wreduce(wdot(Vout + (size_t)(i-2)*D, sZ2, lane));
                    if (lane == 0) E2[warp] = __expf(a);
                }
            }
            // phi row j = i-1 (implicit V[i-1])
            if (gw == i - 1 - tmp) {
                float a = wdot(sZ2, sY1, lane);
                if (hv) a += wdot(g_ZW + (size_t)i*D, sY2, lane);
                a = wreduce(a);
                if (lane == 0) {
                    const float e = __expf(a);
                    atomicAdd(&g_sum2[p], e);
                    g_phi[p] = e;
                }
            }
        }
        // ---- finalize V[i-1] (block-owned rows) ----
        if (i > 0 && warp < RPB) {
            const int r = b*RPB + warp;
            float a = 0.f;
            if (hv) a = wreduce(wdot(sWv2 + warp*D, sY2, lane));
            if (lane == 0) Vout[(size_t)(i-1)*D + r] = sY1[r] + a;
        }
        if (i == N) break;
        __syncthreads();

        // ---- accumulation for step i ----
        if (tmp >= 0) {
            if (warp == 0) {
                float v1 = (lane < NWARP) ? E1[lane] : 0.f;
                float v2 = (lane < NWARP) ? E2[lane] : 0.f;
                v1 = wreduce(v1); v2 = wreduce(v2);
                if (lane == 0) {
                    if (v1 != 0.f) atomicAdd(&g_sum1[p], v1);
                    if (v2 != 0.f) atomicAdd(&g_sum2[p], v2);
                }
            }
            // float4 column accumulation: threads 0..191 intra, 256..447 inter
            if (t < 192) {
                int n1 = i + 1 - b*NWARP;
                if (n1 > NWARP) n1 = NWARP;
                if (n1 > 0) {
                    float4 a = make_float4(0.f, 0.f, 0.f, 0.f);
                    for (int w = 0; w < n1; w++) {
                        const float e = E1[w];
                        float4 v = ((const float4*)(g_V1 + (size_t)(b*NWARP + w)*D))[t];
                        a.x += e*v.x; a.y += e*v.y; a.z += e*v.z; a.w += e*v.w;
                    }
                    float* dst = &g_vacc1[p][t*4];
                    atomicAdd(dst+0, a.x); atomicAdd(dst+1, a.y);
                    atomicAdd(dst+2, a.z); atomicAdd(dst+3, a.w);
                }
            } else if (t >= 256 && t < 448) {
                const int c4 = t - 256;
                const int base2 = tmp + b*NWARP;
                int n2 = i - 1 - base2;          // rows [tmp, i-2]
                if (n2 > NWARP) n2 = NWARP;
                if (n2 > 0) {
                    float4 a = make_float4(0.f, 0.f, 0.f, 0.f);
                    for (int w = 0; w < n2; w++) {
                        const float e = E2[w];
                        float4 v = ((const float4*)(Vout + (size_t)(base2 + w)*D))[c4];
                        a.x += e*v.x; a.y += e*v.y; a.z += e*v.z; a.w += e*v.w;
                    }
                    float* dst = &g_vaccV[p][c4*4];
                    atomicAdd(dst+0, a.x); atomicAdd(dst+1, a.y);
                    atomicAdd(dst+2, a.z); atomicAdd(dst+3, a.w);
                }
            }
        }

        // ---- precompute step i+1 scores (off critical path) ----
        if (preN) {
            float s1v = (lane == 0 && gw <= i + 1) ? __ldg(&g_S1b[(size_t)(i+1)*N + gw]) : 0.f;
            float e = 0.f;
            if (gw <= i + 1) {
                float a = wreduce(wdot(g_KM + (size_t)gw*D, sVtN, lane));
                e = __expf(a + s1v);
            }
            float e2 = 0.f;
            const int j = tmpn + gw;
            if (j <= i - 2) {
                float a = wreduce(wdot(Vout + (size_t)j*D, sZ2N, lane));
                e2 = __expf(a);
            }
            if (lane == 0) { E1n[warp] = e; E2n[warp] = e2; }
        }
        grid_bar(nbar);
    }
}

// ---------------- launch : k_main is launch #4 ----------------
extern "C" void kernel_launch(void* const* d_in, const int* in_sizes, int n_in,
                              void* d_out, int out_size) {
    const float* U       = (const float*)d_in[0];
    const int*   spk     = (const int*)  d_in[1];
    const float* W_intra = (const float*)d_in[2];
    const float* b_intra = (const float*)d_in[3];
    const float* W_inter = (const float*)d_in[4];
    const float* b_inter = (const float*)d_in[5];
    const float* Wq1 = (const float*)d_in[6];  const float* bq1 = (const float*)d_in[7];
    const float* Wk1 = (const float*)d_in[8];  const float* bk1 = (const float*)d_in[9];
    const float* Wv1 = (const float*)d_in[10]; const float* bv1 = (const float*)d_in[11];
    const float* Wq2 = (const float*)d_in[12]; const float* bq2 = (const float*)d_in[13];
    const float* Wk2 = (const float*)d_in[14]; const float* bk2 = (const float*)d_in[15];
    const float* Wv2 = (const float*)d_in[16]; const float* bv2 = (const float*)d_in[17];
    float* Vout = (float*)d_out;
    (void)in_sizes; (void)n_in; (void)out_size; (void)bk2;

    cudaFuncSetAttribute(k_main, cudaFuncAttributeMaxDynamicSharedMemorySize, SMEM_BYTES);

    k_pre1<<<777, 256>>>(spk, Wq1, bq1, b_intra, Wq2, bq2, b_inter,
                         W_intra, W_inter, Wk2, Wv2);                 // 1
    k_pre2<<<1680, 256>>>(U, Wk1, bk1, Wv1, bv1, Wv2);                // 2
    k_pre3<<<2560, 256>>>(Wk2);                                       // 3
    k_main<<<NB, NT, SMEM_BYTES>>>(U, Wv2, bv2, Vout);                // 4
}

// round 10
// speedup vs baseline: 1.3891x; 1.0078x over previous
#include <cuda_runtime.h>
#include <math.h>

#define N 2048
#define D 768
#define SCALE 0.036084391824351615f  /* 1/sqrt(768) */

#define NB 128
#define NT 512
#define NWARP (NT/32)     /* 16 */
#define RPB (D / NB)      /* 6 rows per block */
#define GWTOT (NB*NWARP)  /* 2048 global warps: 1 row per warp */
#define NSL 3             /* triple-buffered accumulators */

/* k_main dynamic smem layout (float slots) */
#define OFF_WV2   0
#define OFF_Y1    (RPB*D)
#define OFF_Y2    (RPB*D + D)
#define OFF_VT    (RPB*D + 2*D)
#define OFF_VTN   (RPB*D + 3*D)
#define OFF_Z2    (RPB*D + 4*D)
#define OFF_Z2N   (RPB*D + 5*D)
#define OFF_TMPI  (RPB*D + 6*D)
#define SMEM_FLOATS (RPB*D + 6*D + N)
#define SMEM_BYTES  (SMEM_FLOATS * 4)

// ---------------- device globals ----------------
__device__ float g_K1[N*D];
__device__ float g_V1[N*D];
__device__ float g_D1[N*D];            // scale*(U@WD^T + bD)
__device__ float g_Q2[N*D];
__device__ float g_Z2[N*D];            // scale*(Q2@Wk2)
__device__ float g_KM[N*D];            // K1 @ M
__device__ float g_ZW[N*D];            // Z2 @ Wv2
__device__ float g_KMW[N*D];           // KM @ Wv2
__device__ float g_S1b[(size_t)N*N];   // D1 @ K1^T (lower tri used)
__device__ float g_M [D*D];            // scale*(Wq1 @ W_intra[:, :D])
__device__ float g_WD[D*D];
__device__ float g_WQ[D*D];
__device__ float g_W2V[D*D];           // Wk2 @ Wv2
__device__ float g_MW[D*D];            // M @ Wv2
__device__ float g_bD[D];
__device__ float g_bQ[D];
__device__ float g_vacc1[NSL][D];
__device__ float g_vaccV[NSL][D];
__device__ float g_sum1[NSL];
__device__ float g_sum2[NSL];
__device__ float g_phi[NSL];
__device__ int   g_tmp[N];
__device__ unsigned long long g_root;

// ---------------- helpers ----------------
__device__ __forceinline__ float wreduce(float a) {
    #pragma unroll
    for (int o = 16; o; o >>= 1) a += __shfl_xor_sync(0xffffffffu, a, o);
    return a;
}

// warp dot over D=768 (192 float4 = 32 lanes x 6)
__device__ __forceinline__ float wdot(const float* __restrict__ a,
                                      const float* __restrict__ b, int lane) {
    const float4* A = (const float4*)a;
    const float4* B = (const float4*)b;
    float s = 0.f;
    #pragma unroll
    for (int u = 0; u < 6; u++) {
        float4 x = A[lane + 32*u], y = B[lane + 32*u];
        s += x.x*y.x + x.y*y.y + x.z*y.z + x.w*y.w;
    }
    return s;
}

// fence-free grid barrier: release-arrive + acquire-poll on one counter.
__device__ __forceinline__ void grid_bar(unsigned long long& nbar) {
    __syncthreads();
    if (threadIdx.x == 0) {
        unsigned long long one = 1ULL;
        asm volatile("red.release.gpu.add.u64 [%0], %1;"
                     :: "l"(&g_root), "l"(one) : "memory");
        const unsigned long long tgt = (nbar + 1) * (unsigned long long)NB;
        unsigned long long v;
        do {
            asm volatile("ld.acquire.gpu.u64 %0, [%1];"
                         : "=l"(v) : "l"(&g_root) : "memory");
        } while (v < tgt);
    }
    nbar++;
    __syncthreads();
}

// ================= GEMM tile bodies =================
#define GBM 64
#define GBN 64
#define GBK 16

__device__ __forceinline__ void gemm_ab_body(const float* __restrict__ A,
                                             const float* __restrict__ B,
                                             int ldb, int boff,
                                             float* __restrict__ C,
                                             int m0, int n0, float alpha) {
    __shared__ float As[GBM][GBK + 1];
    __shared__ float Bs[GBK][GBN];
    const int t = threadIdx.x;
    const int tx = t & 15, ty = t >> 4;
    float acc[4][4] = {};
    for (int k0 = 0; k0 < D; k0 += GBK) {
        for (int x = t; x < GBM*GBK; x += 256) {
            int m = x >> 4, k = x & 15;
            As[m][k] = A[(size_t)(m0 + m)*D + k0 + k];
        }
        for (int x = t; x < GBK*GBN; x += 256) {
            int k = x >> 6, n = x & 63;
            Bs[k][n] = B[(size_t)(k0 + k)*ldb + boff + n0 + n];
        }
        __syncthreads();
        #pragma unroll
        for (int kk = 0; kk < GBK; kk++) {
            float a[4], w[4];
            #pragma unroll
            for (int u = 0; u < 4; u++) a[u] = As[ty*4 + u][kk];
            #pragma unroll
            for (int v = 0; v < 4; v++) w[v] = Bs[kk][tx*4 + v];
            #pragma unroll
            for (int u = 0; u < 4; u++)
                #pragma unroll
                for (int v = 0; v < 4; v++) acc[u][v] += a[u] * w[v];
        }
        __syncthreads();
    }
    #pragma unroll
    for (int u = 0; u < 4; u++)
        #pragma unroll
        for (int v = 0; v < 4; v++)
            C[(size_t)(m0 + ty*4 + u)*D + n0 + tx*4 + v] = alpha * acc[u][v];
}

__device__ __forceinline__ void gemm_nt_body(const float* __restrict__ A,
                                             const float* __restrict__ W,
                                             const float* __restrict__ bias,
                                             float* __restrict__ C, int ldc,
                                             int m0, int n0, float alpha) {
    __shared__ float As[GBM][GBK + 1];
    __shared__ float Ws[GBN][GBK + 1];
    const int t = threadIdx.x;
    const int tx = t & 15, ty = t >> 4;
    float acc[4][4] = {};
    for (int k0 = 0; k0 < D; k0 += GBK) {
        for (int x = t; x < GBM*GBK; x += 256) {
            int m = x >> 4, k = x & 15;
            As[m][k] = A[(size_t)(m0 + m)*D + k0 + k];
        }
        for (int x = t; x < GBN*GBK; x += 256) {
            int n = x >> 4, k = x & 15;
            Ws[n][k] = W[(size_t)(n0 + n)*D + k0 + k];
        }
        __syncthreads();
        #pragma unroll
        for (int kk = 0; kk < GBK; kk++) {
            float a[4], w[4];
            #pragma unroll
            for (int u = 0; u < 4; u++) a[u] = As[ty*4 + u][kk];
            #pragma unroll
            for (int v = 0; v < 4; v++) w[v] = Ws[tx*4 + v][kk];
            #pragma unroll
            for (int u = 0; u < 4; u++)
                #pragma unroll
                for (int v = 0; v < 4; v++) acc[u][v] += a[u] * w[v];
        }
        __syncthreads();
    }
    #pragma unroll
    for (int u = 0; u < 4; u++)
        #pragma unroll
        for (int v = 0; v < 4; v++) {
            int m = m0 + ty*4 + u, n = n0 + tx*4 + v;
            float bb = bias ? bias[n] : 0.f;
            C[(size_t)m*ldc + n] = alpha * (acc[u][v] + bb);
        }
}

// ================= pre1: DD GEMMs {M, WD, WQ, W2V} + setup =================
__global__ void __launch_bounds__(256)
k_pre1(const int* __restrict__ spk,
       const float* __restrict__ Wq1, const float* __restrict__ bq1,
       const float* __restrict__ b_intra,
       const float* __restrict__ Wq2, const float* __restrict__ bq2,
       const float* __restrict__ b_inter,
       const float* __restrict__ W_intra, const float* __restrict__ W_inter,
       const float* __restrict__ Wk2, const float* __restrict__ Wv2) {
    const int blk = blockIdx.x, t = threadIdx.x;
    if (blk < 576) {
        const int z = blk / 144, id = blk % 144;
        const int m0 = (id / 12) * GBM, n0 = (id % 12) * GBN;
        switch (z) {
            case 0: gemm_ab_body(Wq1, W_intra, 2*D, 0, g_M,  m0, n0, SCALE); break;
            case 1: gemm_ab_body(Wq1, W_intra, 2*D, D, g_WD, m0, n0, 1.f);   break;
            case 2: gemm_ab_body(Wq2, W_inter, D,   0, g_WQ, m0, n0, 1.f);   break;
            default: gemm_ab_body(Wk2, Wv2,    D,   0, g_W2V, m0, n0, 1.f);  break;
        }
    } else {
        const int sb = blk - 576;
        if (sb < 8) {
            int i = sb * 256 + t;
            int s = spk[i], r = -1;
            for (int j = i - 1; j >= 0; j--)
                if (spk[j] == s) { r = j; break; }
            g_tmp[i] = r;
        } else if (sb < 200) {
            const int rid = (sb - 8) * 8 + (t >> 5);   // 0..1535
            const int lane = t & 31;
            const int mat = rid >= D;
            const int r = mat ? rid - D : rid;
            const float* W  = mat ? Wq2 : Wq1;
            const float* bv = mat ? b_inter : b_intra;
            float a = 0.f;
            for (int k = lane; k < D; k += 32) a += W[(size_t)r*D + k] * bv[k];
            a = wreduce(a);
            if (lane == 0) {
                if (mat) g_bQ[r] = a + bq2[r];
                else     g_bD[r] = a + bq1[r];
            }
        } else {
            if (t == 0) {
                g_root = 0ULL;
                for (int s = 0; s < NSL; s++) {
                    g_sum1[s] = 0.f; g_sum2[s] = 0.f; g_phi[s] = 0.f;
                }
            }
            for (int c = t; c < D; c += 256)
                for (int s = 0; s < NSL; s++) {
                    g_vacc1[s][c] = 0.f; g_vaccV[s][c] = 0.f;
                }
        }
    }
}

// ================= pre2: ND GEMMs {K1, V1, D1, Q2} + MW =================
__global__ void __launch_bounds__(256)
k_pre2(const float* __restrict__ U,
       const float* __restrict__ Wk1, const float* __restrict__ bk1,
       const float* __restrict__ Wv1, const float* __restrict__ bv1,
       const float* __restrict__ Wv2) {
    const int blk = blockIdx.x;
    if (blk < 1536) {
        const int z = blk / 384, id = blk % 384;
        const int m0 = (id / 12) * GBM, n0 = (id % 12) * GBN;
        switch (z) {
            case 0: gemm_nt_body(U, Wk1,  bk1,  g_K1, D, m0, n0, 1.f);   break;
            case 1: gemm_nt_body(U, Wv1,  bv1,  g_V1, D, m0, n0, 1.f);   break;
            case 2: gemm_nt_body(U, g_WD, g_bD, g_D1, D, m0, n0, SCALE); break;
            default: gemm_nt_body(U, g_WQ, g_bQ, g_Q2, D, m0, n0, 1.f);  break;
        }
    } else {
        const int id = blk - 1536;   // 0..143 : MW = M @ Wv2
        const int m0 = (id / 12) * GBM, n0 = (id % 12) * GBN;
        gemm_ab_body(g_M, Wv2, D, 0, g_MW, m0, n0, 1.f);
    }
}

// ================= pre3: post GEMMs {Z2, KM, ZW, KMW} + S1b (lower tri) =================
__global__ void __launch_bounds__(256)
k_pre3(const float* __restrict__ Wk2) {
    const int blk = blockIdx.x;
    if (blk < 1536) {
        const int z = blk / 384, id = blk % 384;
        const int m0 = (id / 12) * GBM, n0 = (id % 12) * GBN;
        switch (z) {
            case 0: gemm_ab_body(g_Q2, Wk2,   D, 0, g_Z2,  m0, n0, SCALE); break;
            case 1: gemm_ab_body(g_K1, g_M,   D, 0, g_KM,  m0, n0, 1.f);   break;
            case 2: gemm_ab_body(g_Q2, g_W2V, D, 0, g_ZW,  m0, n0, SCALE); break;
            default: gemm_ab_body(g_K1, g_MW, D, 0, g_KMW, m0, n0, 1.f);   break;
        }
    } else {
        const int id = blk - 1536;   // 0..1023 : S1b = D1 @ K1^T (N x N)
        const int bm = id / 32, bn = id % 32;
        if (bn > bm) return;         // only j <= i needed
        gemm_nt_body(g_D1, g_K1, (const float*)0, g_S1b, N, bm*GBM, bn*GBN, 1.f);
    }
}

// ================= main recurrence: pipelined, ONE barrier/step =================
__global__ void __launch_bounds__(NT, 1)
k_main(const float* __restrict__ U,
       const float* __restrict__ Wv2, const float* __restrict__ bv2,
       float* __restrict__ Vout) {
    extern __shared__ float sm[];
    float* sWv2  = sm + OFF_WV2;
    float* sY1   = sm + OFF_Y1;
    float* sY2   = sm + OFF_Y2;
    float* sVt   = sm + OFF_VT;
    float* sVtN  = sm + OFF_VTN;
    float* sZ2   = sm + OFF_Z2;
    float* sZ2N  = sm + OFF_Z2N;
    int*   sTmpI = (int*)(sm + OFF_TMPI);

    __shared__ float sE1[2][NWARP], sE2[2][NWARP];

    const int b = blockIdx.x, t = threadIdx.x;
    const int warp = t >> 5, lane = t & 31;
    const int gw = b * NWARP + warp;   // global warp = global row index

    for (int x = t; x < RPB*D; x += NT)
        sWv2[x] = Wv2[(size_t)(b*RPB)*D + x];
    for (int x = t; x < N; x += NT) sTmpI[x] = g_tmp[x];
    __syncthreads();

    unsigned long long nbar = 0;

    for (int i = 0; i <= N; i++) {
        const int tmp  = (i < N)     ? sTmpI[i]     : -1;
        const int tmpn = (i + 1 < N) ? sTmpI[i + 1] : -1;
        const int p = i % 3, q = (i + 2) % 3, z = (i + 1) % 3;
        const int par = i & 1, parn = par ^ 1;
        bool hv = false;
        const bool fresh = (tmp >= 0) && (tmp == i - 1);
        const bool semi  = (tmp >= 0) && (tmp == i - 2);
        const bool pre   = (tmp >= 0) && (tmp <= i - 3);
        const bool preN  = (i + 1 < N) && (tmpn >= 0) && (tmpn <= i - 2);

        // ---- phase head: y-build + smem loads ----
        if (i > 0) {
            hv = (sTmpI[i-1] >= 0);
            if (hv) {
                float sv1 = 0.f, sv2 = 0.f, pv = 0.f;
                if (lane == 0) {
                    sv1 = __ldcg(&g_sum1[q]);
                    sv2 = __ldcg(&g_sum2[q]);
                    pv  = __ldcg(&g_phi[q]);
                }
                sv1 = __shfl_sync(0xffffffffu, sv1, 0);
                sv2 = __shfl_sync(0xffffffffu, sv2, 0);
                pv  = __shfl_sync(0xffffffffu, pv, 0);
                const float s1i = 1.0f / sv1, s2i = 1.0f / sv2;
                const float* vp2 = Vout + (size_t)(i-2)*D;   // i>=2 when hv
                for (int c = t; c < D; c += NT) {
                    sY1[c] = __ldcg(&g_vacc1[q][c]) * s1i + bv2[c];
                    sY2[c] = (__ldcg(&g_vaccV[q][c]) + pv * vp2[c]) * s2i;
                }
            } else {
                const float* ur = U + (size_t)(i-1)*D;
                for (int c = t; c < D; c += NT) { sY1[c] = ur[c]; sY2[c] = 0.f; }
            }
        }
        if (tmp >= 0) {
            const float* z2r = g_Z2 + (size_t)i*D;
            for (int c = t; c < D; c += NT) sZ2[c] = z2r[c];
            if (semi) {
                const float* vt = Vout + (size_t)tmp*D;      // row i-2: ready
                for (int c = t; c < D; c += NT) sVt[c] = vt[c];
            }
        }
        if (preN) {
            const float* vtn = Vout + (size_t)tmpn*D;        // row <= i-2: ready
            const float* z2n = g_Z2 + (size_t)(i+1)*D;
            for (int c = t; c < D; c += NT) { sVtN[c] = vtn[c]; sZ2N[c] = z2n[c]; }
        }
        if (t < RPB) {
            g_vacc1[z][b*RPB + t] = 0.f;
            g_vaccV[z][b*RPB + t] = 0.f;
        }
        if (b == 0 && t == 0) { g_sum1[z] = 0.f; g_sum2[z] = 0.f; g_phi[z] = 0.f; }
        __syncthreads();

        float* E1  = sE1[par];  float* E2  = sE2[par];
        float* E1n = sE1[parn]; float* E2n = sE2[parn];

        // ---- complete scores for step i ----
        if (tmp >= 0) {
            if (fresh) {
                // intra via implicit V[i-1] = y1 + Wv2*y2
                float s1v = (lane == 0 && gw <= i) ? __ldg(&g_S1b[(size_t)i*N + gw]) : 0.f;
                float e = 0.f;
                if (gw <= i) {
                    float a = wdot(g_KM + (size_t)gw*D, sY1, lane);
                    if (hv) a += wdot(g_KMW + (size_t)gw*D, sY2, lane);
                    a = wreduce(a);
                    e = __expf(a + s1v);
                }
                if (lane == 0) { E1[warp] = e; E2[warp] = 0.f; }   // window = {i-1} (phi)
            } else if (semi) {
                float s1v = (lane == 0 && gw <= i) ? __ldg(&g_S1b[(size_t)i*N + gw]) : 0.f;
                float e = 0.f;
                if (gw <= i) {
                    float a = wreduce(wdot(g_KM + (size_t)gw*D, sVt, lane));
                    e = __expf(a + s1v);
                }
                float e2 = 0.f;
                if (gw == 0) {   // inter direct row j = tmp = i-2
                    float a = wreduce(wdot(Vout + (size_t)(i-2)*D, sZ2, lane));
                    e2 = __expf(a);
                }
                if (lane == 0) { E1[warp] = e; E2[warp] = e2; }
            } else if (pre) {
                // E1/E2 precomputed last phase; add inter row j = i-2 now
                if (gw == i - 2 - tmp) {
                    float a = wreduce(wdot(Vout + (size_t)(i-2)*D, sZ2, lane));
                    if (lane == 0) E2[warp] = __expf(a);
                }
            }
            // phi row j = i-1 (implicit V[i-1])
            if (gw == i - 1 - tmp) {
                float a = wdot(sZ2, sY1, lane);
                if (hv) a += wdot(g_ZW + (size_t)i*D, sY2, lane);
                a = wreduce(a);
                if (lane == 0) {
                    const float e = __expf(a);
                    atomicAdd(&g_sum2[p], e);
                    g_phi[p] = e;
                }
            }
        }
        // ---- finalize V[i-1] (block-owned rows) ----
        if (i > 0 && warp < RPB) {
            const int r = b*RPB + warp;
            float a = 0.f;
            if (hv) a = wreduce(wdot(sWv2 + warp*D, sY2, lane));
            if (lane == 0) Vout[(size_t)(i-1)*D + r] = sY1[r] + a;
        }
        if (i == N) break;
        __syncthreads();

        // ---- accumulation for step i ----
        if (tmp >= 0) {
            if (warp == 0) {
                float v1 = (lane < NWARP) ? E1[lane] : 0.f;
                float v2 = (lane < NWARP) ? E2[lane] : 0.f;
                v1 = wreduce(v1); v2 = wreduce(v2);
                if (lane == 0) {
                    if (v1 != 0.f) atomicAdd(&g_sum1[p], v1);
                    if (v2 != 0.f) atomicAdd(&g_sum2[p], v2);
                }
            }
            // float4 column accumulation: threads 0..191 intra, 256..447 inter
            if (t < 192) {
                int n1 = i + 1 - b*NWARP;
                if (n1 > NWARP) n1 = NWARP;
                if (n1 > 0) {
                    float4 a = make_float4(0.f, 0.f, 0.f, 0.f);
                    for (int w = 0; w < n1; w++) {
                        const float e = E1[w];
                        float4 v = ((const float4*)(g_V1 + (size_t)(b*NWARP + w)*D))[t];
                        a.x += e*v.x; a.y += e*v.y; a.z += e*v.z; a.w += e*v.w;
                    }
                    float* dst = &g_vacc1[p][t*4];
                    atomicAdd(dst+0, a.x); atomicAdd(dst+1, a.y);
                    atomicAdd(dst+2, a.z); atomicAdd(dst+3, a.w);
                }
            } else if (t >= 256 && t < 448) {
                const int c4 = t - 256;
                const int base2 = tmp + b*NWARP;
                int n2 = i - 1 - base2;          // rows [tmp, i-2]
                if (n2 > NWARP) n2 = NWARP;
                if (n2 > 0) {
                    float4 a = make_float4(0.f, 0.f, 0.f, 0.f);
                    for (int w = 0; w < n2; w++) {
                        const float e = E2[w];
                        float4 v = ((const float4*)(Vout + (size_t)(base2 + w)*D))[c4];
                        a.x += e*v.x; a.y += e*v.y; a.z += e*v.z; a.w += e*v.w;
                    }
                    float* dst = &g_vaccV[p][c4*4];
                    atomicAdd(dst+0, a.x); atomicAdd(dst+1, a.y);
                    atomicAdd(dst+2, a.z); atomicAdd(dst+3, a.w);
                }
            }
        }

        // ---- precompute step i+1 scores (off critical path) ----
        if (preN) {
            float s1v = (lane == 0 && gw <= i + 1) ? __ldg(&g_S1b[(size_t)(i+1)*N + gw]) : 0.f;
            float e = 0.f;
            if (gw <= i + 1) {
                float a = wreduce(wdot(g_KM + (size_t)gw*D, sVtN, lane));
                e = __expf(a + s1v);
            }
            float e2 = 0.f;
            const int j = tmpn + gw;
            if (j <= i - 2) {
                float a = wreduce(wdot(Vout + (size_t)j*D, sZ2N, lane));
                e2 = __expf(a);
            }
            if (lane == 0) { E1n[warp] = e; E2n[warp] = e2; }
        }
        grid_bar(nbar);
    }
}

// ---------------- launch : k_main is launch #4 ----------------
extern "C" void kernel_launch(void* const* d_in, const int* in_sizes, int n_in,
                              void* d_out, int out_size) {
    const float* U       = (const float*)d_in[0];
    const int*   spk     = (const int*)  d_in[1];
    const float* W_intra = (const float*)d_in[2];
    const float* b_intra = (const float*)d_in[3];
    const float* W_inter = (const float*)d_in[4];
    const float* b_inter = (const float*)d_in[5];
    const float* Wq1 = (const float*)d_in[6];  const float* bq1 = (const float*)d_in[7];
    const float* Wk1 = (const float*)d_in[8];  const float* bk1 = (const float*)d_in[9];
    const float* Wv1 = (const float*)d_in[10]; const float* bv1 = (const float*)d_in[11];
    const float* Wq2 = (const float*)d_in[12]; const float* bq2 = (const float*)d_in[13];
    const float* Wk2 = (const float*)d_in[14]; const float* bk2 = (const float*)d_in[15];
    const float* Wv2 = (const float*)d_in[16]; const float* bv2 = (const float*)d_in[17];
    float* Vout = (float*)d_out;
    (void)in_sizes; (void)n_in; (void)out_size; (void)bk2;

    cudaFuncSetAttribute(k_main, cudaFuncAttributeMaxDynamicSharedMemorySize, SMEM_BYTES);

    k_pre1<<<777, 256>>>(spk, Wq1, bq1, b_intra, Wq2, bq2, b_inter,
                         W_intra, W_inter, Wk2, Wv2);                 // 1
    k_pre2<<<1680, 256>>>(U, Wk1, bk1, Wv1, bv1, Wv2);                // 2
    k_pre3<<<2560, 256>>>(Wk2);                                       // 3
    k_main<<<NB, NT, SMEM_BYTES>>>(U, Wv2, bv2, Vout);                // 4
}

// round 11
// speedup vs baseline: 1.5373x; 1.1067x over previous
#include <cuda_runtime.h>
#include <math.h>

#define N 2048
#define D 768
#define SCALE 0.036084391824351615f  /* 1/sqrt(768) */

#define NB 128
#define NT 512
#define NWARP (NT/32)     /* 16 */
#define RPB (D / NB)      /* 6 rows per block */
#define NSL 3             /* triple-buffered accumulators */

/* k_main dynamic smem layout (float slots) */
#define OFF_WV2   0
#define OFF_Y1    (RPB*D)
#define OFF_Y2    (RPB*D + D)
#define OFF_VT    (RPB*D + 2*D)
#define OFF_VTN   (RPB*D + 3*D)
#define OFF_Z2    (RPB*D + 4*D)
#define OFF_Z2N   (RPB*D + 5*D)
#define OFF_TMPI  (RPB*D + 6*D)
#define SMEM_FLOATS (RPB*D + 6*D + N)
#define SMEM_BYTES  (SMEM_FLOATS * 4)

// ---------------- device globals ----------------
__device__ float g_K1[N*D];
__device__ float g_V1[N*D];
__device__ float g_D1[N*D];            // scale*(U@WD^T + bD)
__device__ float g_Q2[N*D];
__device__ float g_Z2[N*D];            // scale*(Q2@Wk2)
__device__ float g_KM[N*D];            // K1 @ M
__device__ float g_ZW[N*D];            // Z2 @ Wv2
__device__ float g_KMW[N*D];           // KM @ Wv2
__device__ float g_S1b[(size_t)N*N];   // D1 @ K1^T (lower tri used)
__device__ float g_M [D*D];            // scale*(Wq1 @ W_intra[:, :D])
__device__ float g_WD[D*D];
__device__ float g_WQ[D*D];
__device__ float g_W2V[D*D];           // Wk2 @ Wv2
__device__ float g_MW[D*D];            // M @ Wv2
__device__ float g_bD[D];
__device__ float g_bQ[D];
__device__ float g_vacc1[NSL][D];
__device__ float g_vaccV[NSL][D];
__device__ float g_sum1[NSL];
__device__ float g_sum2[NSL];
__device__ float g_phi[NSL];
__device__ int   g_tmp[N];
__device__ unsigned long long g_root;

// ---------------- helpers ----------------
__device__ __forceinline__ float wreduce(float a) {
    #pragma unroll
    for (int o = 16; o; o >>= 1) a += __shfl_xor_sync(0xffffffffu, a, o);
    return a;
}

// warp dot over D=768 (192 float4 = 32 lanes x 6)
__device__ __forceinline__ float wdot(const float* __restrict__ a,
                                      const float* __restrict__ b, int lane) {
    const float4* A = (const float4*)a;
    const float4* B = (const float4*)b;
    float s = 0.f;
    #pragma unroll
    for (int u = 0; u < 6; u++) {
        float4 x = A[lane + 32*u], y = B[lane + 32*u];
        s += x.x*y.x + x.y*y.y + x.z*y.z + x.w*y.w;
    }
    return s;
}

// split-phase fence-free grid barrier
__device__ __forceinline__ void bar_arrive() {
    __syncthreads();
    if (threadIdx.x == 0) {
        unsigned long long one = 1ULL;
        asm volatile("red.release.gpu.add.u64 [%0], %1;"
                     :: "l"(&g_root), "l"(one) : "memory");
    }
}
__device__ __forceinline__ void bar_wait(unsigned long long& nbar) {
    if (threadIdx.x == 0) {
        const unsigned long long tgt = (nbar + 1) * (unsigned long long)NB;
        unsigned long long v;
        do {
            asm volatile("ld.acquire.gpu.u64 %0, [%1];"
                         : "=l"(v) : "l"(&g_root) : "memory");
        } while (v < tgt);
    }
    nbar++;
    __syncthreads();
}

// ================= GEMM tile bodies =================
#define GBM 64
#define GBN 64
#define GBK 16

__device__ __forceinline__ void gemm_ab_body(const float* __restrict__ A,
                                             const float* __restrict__ B,
                                             int ldb, int boff,
                                             float* __restrict__ C,
                                             int m0, int n0, float alpha) {
    __shared__ float As[GBM][GBK + 1];
    __shared__ float Bs[GBK][GBN];
    const int t = threadIdx.x;
    const int tx = t & 15, ty = t >> 4;
    float acc[4][4] = {};
    for (int k0 = 0; k0 < D; k0 += GBK) {
        for (int x = t; x < GBM*GBK; x += 256) {
            int m = x >> 4, k = x & 15;
            As[m][k] = A[(size_t)(m0 + m)*D + k0 + k];
        }
        for (int x = t; x < GBK*GBN; x += 256) {
            int k = x >> 6, n = x & 63;
            Bs[k][n] = B[(size_t)(k0 + k)*ldb + boff + n0 + n];
        }
        __syncthreads();
        #pragma unroll
        for (int kk = 0; kk < GBK; kk++) {
            float a[4], w[4];
            #pragma unroll
            for (int u = 0; u < 4; u++) a[u] = As[ty*4 + u][kk];
            #pragma unroll
            for (int v = 0; v < 4; v++) w[v] = Bs[kk][tx*4 + v];
            #pragma unroll
            for (int u = 0; u < 4; u++)
                #pragma unroll
                for (int v = 0; v < 4; v++) acc[u][v] += a[u] * w[v];
        }
        __syncthreads();
    }
    #pragma unroll
    for (int u = 0; u < 4; u++)
        #pragma unroll
        for (int v = 0; v < 4; v++)
            C[(size_t)(m0 + ty*4 + u)*D + n0 + tx*4 + v] = alpha * acc[u][v];
}

__device__ __forceinline__ void gemm_nt_body(const float* __restrict__ A,
                                             const float* __restrict__ W,
                                             const float* __restrict__ bias,
                                             float* __restrict__ C, int ldc,
                                             int m0, int n0, float alpha) {
    __shared__ float As[GBM][GBK + 1];
    __shared__ float Ws[GBN][GBK + 1];
    const int t = threadIdx.x;
    const int tx = t & 15, ty = t >> 4;
    float acc[4][4] = {};
    for (int k0 = 0; k0 < D; k0 += GBK) {
        for (int x = t; x < GBM*GBK; x += 256) {
            int m = x >> 4, k = x & 15;
            As[m][k] = A[(size_t)(m0 + m)*D + k0 + k];
        }
        for (int x = t; x < GBN*GBK; x += 256) {
            int n = x >> 4, k = x & 15;
            Ws[n][k] = W[(size_t)(n0 + n)*D + k0 + k];
        }
        __syncthreads();
        #pragma unroll
        for (int kk = 0; kk < GBK; kk++) {
            float a[4], w[4];
            #pragma unroll
            for (int u = 0; u < 4; u++) a[u] = As[ty*4 + u][kk];
            #pragma unroll
            for (int v = 0; v < 4; v++) w[v] = Ws[tx*4 + v][kk];
            #pragma unroll
            for (int u = 0; u < 4; u++)
                #pragma unroll
                for (int v = 0; v < 4; v++) acc[u][v] += a[u] * w[v];
        }
        __syncthreads();
    }
    #pragma unroll
    for (int u = 0; u < 4; u++)
        #pragma unroll
        for (int v = 0; v < 4; v++) {
            int m = m0 + ty*4 + u, n = n0 + tx*4 + v;
            float bb = bias ? bias[n] : 0.f;
            C[(size_t)m*ldc + n] = alpha * (acc[u][v] + bb);
        }
}

// ================= pre1: DD GEMMs {M, WD, WQ, W2V} + setup =================
__global__ void __launch_bounds__(256)
k_pre1(const int* __restrict__ spk,
       const float* __restrict__ Wq1, const float* __restrict__ bq1,
       const float* __restrict__ b_intra,
       const float* __restrict__ Wq2, const float* __restrict__ bq2,
       const float* __restrict__ b_inter,
       const float* __restrict__ W_intra, const float* __restrict__ W_inter,
       const float* __restrict__ Wk2, const float* __restrict__ Wv2) {
    const int blk = blockIdx.x, t = threadIdx.x;
    if (blk < 576) {
        const int z = blk / 144, id = blk % 144;
        const int m0 = (id / 12) * GBM, n0 = (id % 12) * GBN;
        switch (z) {
            case 0: gemm_ab_body(Wq1, W_intra, 2*D, 0, g_M,  m0, n0, SCALE); break;
            case 1: gemm_ab_body(Wq1, W_intra, 2*D, D, g_WD, m0, n0, 1.f);   break;
            case 2: gemm_ab_body(Wq2, W_inter, D,   0, g_WQ, m0, n0, 1.f);   break;
            default: gemm_ab_body(Wk2, Wv2,    D,   0, g_W2V, m0, n0, 1.f);  break;
        }
    } else {
        const int sb = blk - 576;
        if (sb < 8) {
            int i = sb * 256 + t;
            int s = spk[i], r = -1;
            for (int j = i - 1; j >= 0; j--)
                if (spk[j] == s) { r = j; break; }
            g_tmp[i] = r;
        } else if (sb < 200) {
            const int rid = (sb - 8) * 8 + (t >> 5);   // 0..1535
            const int lane = t & 31;
            const int mat = rid >= D;
            const int r = mat ? rid - D : rid;
            const float* W  = mat ? Wq2 : Wq1;
            const float* bv = mat ? b_inter : b_intra;
            float a = 0.f;
            for (int k = lane; k < D; k += 32) a += W[(size_t)r*D + k] * bv[k];
            a = wreduce(a);
            if (lane == 0) {
                if (mat) g_bQ[r] = a + bq2[r];
                else     g_bD[r] = a + bq1[r];
            }
        } else {
            if (t == 0) {
                g_root = 0ULL;
                for (int s = 0; s < NSL; s++) {
                    g_sum1[s] = 0.f; g_sum2[s] = 0.f; g_phi[s] = 0.f;
                }
            }
            for (int c = t; c < D; c += 256)
                for (int s = 0; s < NSL; s++) {
                    g_vacc1[s][c] = 0.f; g_vaccV[s][c] = 0.f;
                }
        }
    }
}

// ================= pre2: ND GEMMs {K1, V1, D1, Q2} + MW =================
__global__ void __launch_bounds__(256)
k_pre2(const float* __restrict__ U,
       const float* __restrict__ Wk1, const float* __restrict__ bk1,
       const float* __restrict__ Wv1, const float* __restrict__ bv1,
       const float* __restrict__ Wv2) {
    const int blk = blockIdx.x;
    if (blk < 1536) {
        const int z = blk / 384, id = blk % 384;
        const int m0 = (id / 12) * GBM, n0 = (id % 12) * GBN;
        switch (z) {
            case 0: gemm_nt_body(U, Wk1,  bk1,  g_K1, D, m0, n0, 1.f);   break;
            case 1: gemm_nt_body(U, Wv1,  bv1,  g_V1, D, m0, n0, 1.f);   break;
            case 2: gemm_nt_body(U, g_WD, g_bD, g_D1, D, m0, n0, SCALE); break;
            default: gemm_nt_body(U, g_WQ, g_bQ, g_Q2, D, m0, n0, 1.f);  break;
        }
    } else {
        const int id = blk - 1536;   // 0..143 : MW = M @ Wv2
        const int m0 = (id / 12) * GBM, n0 = (id % 12) * GBN;
        gemm_ab_body(g_M, Wv2, D, 0, g_MW, m0, n0, 1.f);
    }
}

// ================= pre3: post GEMMs {Z2, KM, ZW, KMW} + S1b (lower tri) =================
__global__ void __launch_bounds__(256)
k_pre3(const float* __restrict__ Wk2) {
    const int blk = blockIdx.x;
    if (blk < 1536) {
        const int z = blk / 384, id = blk % 384;
        const int m0 = (id / 12) * GBM, n0 = (id % 12) * GBN;
        switch (z) {
            case 0: gemm_ab_body(g_Q2, Wk2,   D, 0, g_Z2,  m0, n0, SCALE); break;
            case 1: gemm_ab_body(g_K1, g_M,   D, 0, g_KM,  m0, n0, 1.f);   break;
            case 2: gemm_ab_body(g_Q2, g_W2V, D, 0, g_ZW,  m0, n0, SCALE); break;
            default: gemm_ab_body(g_K1, g_MW, D, 0, g_KMW, m0, n0, 1.f);   break;
        }
    } else {
        const int id = blk - 1536;   // 0..1023 : S1b = D1 @ K1^T (N x N)
        const int bm = id / 32, bn = id % 32;
        if (bn > bm) return;         // only j <= i needed
        gemm_nt_body(g_D1, g_K1, (const float*)0, g_S1b, N, bm*GBM, bn*GBN, 1.f);
    }
}

// ================= main recurrence: split-phase barrier, overlap after arrive =================
__global__ void __launch_bounds__(NT, 1)
k_main(const float* __restrict__ U,
       const float* __restrict__ Wv2, const float* __restrict__ bv2,
       float* __restrict__ Vout) {
    extern __shared__ float sm[];
    float* sWv2  = sm + OFF_WV2;
    float* sY1   = sm + OFF_Y1;
    float* sY2   = sm + OFF_Y2;
    float* sVt   = sm + OFF_VT;
    float* sVtN  = sm + OFF_VTN;
    float* sZ2   = sm + OFF_Z2;
    float* sZ2N  = sm + OFF_Z2N;
    int*   sTmpI = (int*)(sm + OFF_TMPI);

    __shared__ float sE1[2][NWARP], sE2[2][NWARP];

    const int b = blockIdx.x, t = threadIdx.x;
    const int warp = t >> 5, lane = t & 31;
    const int gw = b * NWARP + warp;   // global warp = global row index

    for (int x = t; x < RPB*D; x += NT)
        sWv2[x] = Wv2[(size_t)(b*RPB)*D + x];
    for (int x = t; x < N; x += NT) sTmpI[x] = g_tmp[x];
    __syncthreads();

    unsigned long long nbar = 0;

    for (int i = 0; i <= N; i++) {
        const int tmp  = (i < N)     ? sTmpI[i]     : -1;
        const int tmpn = (i + 1 < N) ? sTmpI[i + 1] : -1;
        const int p = i % 3, q = (i + 2) % 3, z = (i + 1) % 3;
        const int par = i & 1, parn = par ^ 1;
        bool hv = false;
        const bool fresh = (tmp >= 0) && (tmp == i - 1);
        const bool semi  = (tmp >= 0) && (tmp == i - 2);
        const bool pre   = (tmp >= 0) && (tmp <= i - 3);
        const bool preN  = (i + 1 < N) && (tmpn >= 0) && (tmpn <= i - 2);

        // ---- phase head: y-build + smem loads ----
        if (i > 0) {
            hv = (sTmpI[i-1] >= 0);
            if (hv) {
                float sv1 = 0.f, sv2 = 0.f, pv = 0.f;
                if (lane == 0) {
                    sv1 = __ldcg(&g_sum1[q]);
                    sv2 = __ldcg(&g_sum2[q]);
                    pv  = __ldcg(&g_phi[q]);
                }
                sv1 = __shfl_sync(0xffffffffu, sv1, 0);
                sv2 = __shfl_sync(0xffffffffu, sv2, 0);
                pv  = __shfl_sync(0xffffffffu, pv, 0);
                const float s1i = 1.0f / sv1, s2i = 1.0f / sv2;
                const float* vp2 = Vout + (size_t)(i-2)*D;   // i>=2 when hv
                for (int c = t; c < D; c += NT) {
                    sY1[c] = __ldcg(&g_vacc1[q][c]) * s1i + bv2[c];
                    sY2[c] = (__ldcg(&g_vaccV[q][c]) + pv * vp2[c]) * s2i;
                }
            } else {
                const float* ur = U + (size_t)(i-1)*D;
                for (int c = t; c < D; c += NT) { sY1[c] = ur[c]; sY2[c] = 0.f; }
            }
        }
        if (tmp >= 0) {
            const float* z2r = g_Z2 + (size_t)i*D;
            for (int c = t; c < D; c += NT) sZ2[c] = z2r[c];
            if (semi) {
                const float* vt = Vout + (size_t)tmp*D;      // row i-2: ready
                for (int c = t; c < D; c += NT) sVt[c] = vt[c];
            }
        }
        if (preN) {
            const float* vtn = Vout + (size_t)tmpn*D;        // row <= i-2: ready
            const float* z2n = g_Z2 + (size_t)(i+1)*D;
            for (int c = t; c < D; c += NT) { sVtN[c] = vtn[c]; sZ2N[c] = z2n[c]; }
        }
        if (t < RPB) {
            g_vacc1[z][b*RPB + t] = 0.f;
            g_vaccV[z][b*RPB + t] = 0.f;
        }
        if (b == 0 && t == 0) { g_sum1[z] = 0.f; g_sum2[z] = 0.f; g_phi[z] = 0.f; }
        __syncthreads();

        float* E1  = sE1[par];  float* E2  = sE2[par];
        float* E1n = sE1[parn]; float* E2n = sE2[parn];

        // ---- on-chain scores for step i ----
        if (tmp >= 0) {
            if (fresh) {
                // intra via implicit V[i-1] = y1 + Wv2*y2
                float s1v = (lane == 0 && gw <= i) ? __ldg(&g_S1b[(size_t)i*N + gw]) : 0.f;
                float e = 0.f;
                if (gw <= i) {
                    float a = wdot(g_KM + (size_t)gw*D, sY1, lane);
                    if (hv) a += wdot(g_KMW + (size_t)gw*D, sY2, lane);
                    a = wreduce(a);
                    e = __expf(a + s1v);
                }
                if (lane == 0) { E1[warp] = e; E2[warp] = 0.f; }   // window = {i-1} (phi)
            } else if (semi) {
                float s1v = (lane == 0 && gw <= i) ? __ldg(&g_S1b[(size_t)i*N + gw]) : 0.f;
                float e = 0.f;
                if (gw <= i) {
                    float a = wreduce(wdot(g_KM + (size_t)gw*D, sVt, lane));
                    e = __expf(a + s1v);
                }
                float e2 = 0.f;
                if (gw == 0) {   // inter direct row j = tmp = i-2
                    float a = wreduce(wdot(Vout + (size_t)(i-2)*D, sZ2, lane));
                    e2 = __expf(a);
                }
                if (lane == 0) { E1[warp] = e; E2[warp] = e2; }
            } else if (pre) {
                // E1/E2 precomputed in previous phase's overlap; add boundary row j = i-2
                if (gw == i - 2 - tmp) {
                    float a = wreduce(wdot(Vout + (size_t)(i-2)*D, sZ2, lane));
                    if (lane == 0) E2[warp] = __expf(a);
                }
            }
            // phi row j = i-1 (implicit V[i-1])
            if (gw == i - 1 - tmp) {
                float a = wdot(sZ2, sY1, lane);
                if (hv) a += wdot(g_ZW + (size_t)i*D, sY2, lane);
                a = wreduce(a);
                if (lane == 0) {
                    const float e = __expf(a);
                    atomicAdd(&g_sum2[p], e);
                    g_phi[p] = e;
                }
            }
        }
        // ---- finalize V[i-1] (block-owned rows) ----
        if (i > 0 && warp < RPB) {
            const int r = b*RPB + warp;
            float a = 0.f;
            if (hv) a = wreduce(wdot(sWv2 + warp*D, sY2, lane));
            if (lane == 0) Vout[(size_t)(i-1)*D + r] = sY1[r] + a;
        }
        if (i == N) break;
        __syncthreads();

        // ---- accumulation for step i (E buffers complete now) ----
        if (tmp >= 0) {
            if (warp == 0) {
                float v1 = (lane < NWARP) ? E1[lane] : 0.f;
                float v2 = (lane < NWARP) ? E2[lane] : 0.f;
                v1 = wreduce(v1); v2 = wreduce(v2);
                if (lane == 0) {
                    if (v1 != 0.f) atomicAdd(&g_sum1[p], v1);
                    if (v2 != 0.f) atomicAdd(&g_sum2[p], v2);
                }
            }
            // fully unrolled float4 accumulation; e==0 rows contribute nothing
            if (t < 192) {
                const int rbase = b*NWARP;
                if (rbase <= i) {
                    float4 a = make_float4(0.f, 0.f, 0.f, 0.f);
                    #pragma unroll
                    for (int w = 0; w < NWARP; w++) {
                        const float e = E1[w];
                        const float4 v = ((const float4*)(g_V1 + (size_t)(rbase + w)*D))[t];
                        a.x += e*v.x; a.y += e*v.y; a.z += e*v.z; a.w += e*v.w;
                    }
                    float* dst = &g_vacc1[p][t*4];
                    atomicAdd(dst+0, a.x); atomicAdd(dst+1, a.y);
                    atomicAdd(dst+2, a.z); atomicAdd(dst+3, a.w);
                }
            } else if (t >= 256 && t < 448) {
                const int c4 = t - 256;
                const int base2 = tmp + b*NWARP;
                if (base2 <= i - 2) {
                    float4 a = make_float4(0.f, 0.f, 0.f, 0.f);
                    #pragma unroll
                    for (int w = 0; w < NWARP; w++) {
                        const float e = E2[w];
                        int j = base2 + w; if (j > N - 1) j = N - 1;   // e==0 there
                        const float4 v = ((const float4*)(Vout + (size_t)j*D))[c4];
                        a.x += e*v.x; a.y += e*v.y; a.z += e*v.z; a.w += e*v.w;
                    }
                    float* dst = &g_vaccV[p][c4*4];
                    atomicAdd(dst+0, a.x); atomicAdd(dst+1, a.y);
                    atomicAdd(dst+2, a.z); atomicAdd(dst+3, a.w);
                }
            }
        }

        // ---- ARRIVE, then overlap: precompute step i+1 scores ----
        bar_arrive();
        if (preN) {
            float s1v = (lane == 0 && gw <= i + 1) ? __ldg(&g_S1b[(size_t)(i+1)*N + gw]) : 0.f;
            float e = 0.f;
            if (gw <= i + 1) {
                float a = wreduce(wdot(g_KM + (size_t)gw*D, sVtN, lane));
                e = __expf(a + s1v);
            }
            float e2 = 0.f;
            const int j = tmpn + gw;
            if (j <= i - 2) {     // rows sealed by barrier i-1 (already passed)
                float a = wreduce(wdot(Vout + (size_t)j*D, sZ2N, lane));
                e2 = __expf(a);
            }
            if (lane == 0) { E1n[warp] = e; E2n[warp] = e2; }
        }
        bar_wait(nbar);
    }
}

// ---------------- launch : k_main is launch #4 ----------------
extern "C" void kernel_launch(void* const* d_in, const int* in_sizes, int n_in,
                              void* d_out, int out_size) {
    const float* U       = (const float*)d_in[0];
    const int*   spk     = (const int*)  d_in[1];
    const float* W_intra = (const float*)d_in[2];
    const float* b_intra = (const float*)d_in[3];
    const float* W_inter = (const float*)d_in[4];
    const float* b_inter = (const float*)d_in[5];
    const float* Wq1 = (const float*)d_in[6];  const float* bq1 = (const float*)d_in[7];
    const float* Wk1 = (const float*)d_in[8];  const float* bk1 = (const float*)d_in[9];
    const float* Wv1 = (const float*)d_in[10]; const float* bv1 = (const float*)d_in[11];
    const float* Wq2 = (const float*)d_in[12]; const float* bq2 = (const float*)d_in[13];
    const float* Wk2 = (const float*)d_in[14]; const float* bk2 = (const float*)d_in[15];
    const float* Wv2 = (const float*)d_in[16]; const float* bv2 = (const float*)d_in[17];
    float* Vout = (float*)d_out;
    (void)in_sizes; (void)n_in; (void)out_size; (void)bk2;

    cudaFuncSetAttribute(k_main, cudaFuncAttributeMaxDynamicSharedMemorySize, SMEM_BYTES);

    k_pre1<<<777, 256>>>(spk, Wq1, bq1, b_intra, Wq2, bq2, b_inter,
                         W_intra, W_inter, Wk2, Wv2);                 // 1
    k_pre2<<<1680, 256>>>(U, Wk1, bk1, Wv1, bv1, Wv2);                // 2
    k_pre3<<<2560, 256>>>(Wk2);                                       // 3
    k_main<<<NB, NT, SMEM_BYTES>>>(U, Wv2, bv2, Vout);                // 4
}

// round 12
// speedup vs baseline: 1.6643x; 1.0826x over previous
#include <cuda_runtime.h>
#include <math.h>

#define N 2048
#define D 768
#define SCALE 0.036084391824351615f  /* 1/sqrt(768) */

#define NB 128
#define NT 512
#define NWARP (NT/32)     /* 16 */
#define RPB (D / NB)      /* 6 rows per block */
#define NSL 4             /* quad-buffered accumulators */

/* k_main dynamic smem layout (float slots) */
#define OFF_WV2   0
#define OFF_Y1    (RPB*D)
#define OFF_Y2    (RPB*D + D)
#define OFF_VTN   (RPB*D + 2*D)
#define OFF_Z2B   (RPB*D + 3*D)            /* 2 rows */
#define OFF_ZWB   (RPB*D + 5*D)            /* 2 rows */
#define OFF_TMPI  (RPB*D + 7*D)
#define SMEM_FLOATS (RPB*D + 7*D + N)
#define SMEM_BYTES  (SMEM_FLOATS * 4)

// ---------------- device globals ----------------
__device__ float g_K1[N*D];
__device__ float g_V1[N*D];
__device__ float g_D1[N*D];            // scale*(U@WD^T + bD)
__device__ float g_Q2[N*D];
__device__ float g_Z2[N*D];            // scale*(Q2@Wk2)
__device__ float g_KM[N*D];            // K1 @ M
__device__ float g_ZW[N*D];            // Z2 @ Wv2
__device__ float g_KMW[N*D];           // KM @ Wv2
__device__ float g_S1b[(size_t)N*N];   // D1 @ K1^T (lower tri used)
__device__ float g_M [D*D];            // scale*(Wq1 @ W_intra[:, :D])
__device__ float g_WD[D*D];
__device__ float g_WQ[D*D];
__device__ float g_W2V[D*D];           // Wk2 @ Wv2
__device__ float g_MW[D*D];            // M @ Wv2
__device__ float g_bD[D];
__device__ float g_bQ[D];
__device__ float g_vacc1[NSL][D];
__device__ float g_vaccV[NSL][D];
__device__ float g_sum1[NSL];
__device__ float g_sum2[NSL];
__device__ float g_phi[NSL];           // deferred inter row s-1
__device__ float g_psi[NSL];           // deferred inter row s-2
__device__ int   g_tmp[N];
__device__ unsigned long long g_root;

// ---------------- helpers ----------------
__device__ __forceinline__ float wreduce(float a) {
    #pragma unroll
    for (int o = 16; o; o >>= 1) a += __shfl_xor_sync(0xffffffffu, a, o);
    return a;
}

__device__ __forceinline__ float wdot(const float* __restrict__ a,
                                      const float* __restrict__ b, int lane) {
    const float4* A = (const float4*)a;
    const float4* B = (const float4*)b;
    float s = 0.f;
    #pragma unroll
    for (int u = 0; u < 6; u++) {
        float4 x = A[lane + 32*u], y = B[lane + 32*u];
        s += x.x*y.x + x.y*y.y + x.z*y.z + x.w*y.w;
    }
    return s;
}

// split-phase fence-free grid barrier
__device__ __forceinline__ void bar_arrive() {
    __syncthreads();
    if (threadIdx.x == 0) {
        unsigned long long one = 1ULL;
        asm volatile("red.release.gpu.add.u64 [%0], %1;"
                     :: "l"(&g_root), "l"(one) : "memory");
    }
}
__device__ __forceinline__ void bar_wait(unsigned long long& nbar) {
    if (threadIdx.x == 0) {
        const unsigned long long tgt = (nbar + 1) * (unsigned long long)NB;
        unsigned long long v;
        do {
            asm volatile("ld.acquire.gpu.u64 %0, [%1];"
                         : "=l"(v) : "l"(&g_root) : "memory");
        } while (v < tgt);
    }
    nbar++;
    __syncthreads();
}

// ================= GEMM tile bodies =================
#define GBM 64
#define GBN 64
#define GBK 16

__device__ __forceinline__ void gemm_ab_body(const float* __restrict__ A,
                                             const float* __restrict__ B,
                                             int ldb, int boff,
                                             float* __restrict__ C,
                                             int m0, int n0, float alpha) {
    __shared__ float As[GBM][GBK + 1];
    __shared__ float Bs[GBK][GBN];
    const int t = threadIdx.x;
    const int tx = t & 15, ty = t >> 4;
    float acc[4][4] = {};
    for (int k0 = 0; k0 < D; k0 += GBK) {
        for (int x = t; x < GBM*GBK; x += 256) {
            int m = x >> 4, k = x & 15;
            As[m][k] = A[(size_t)(m0 + m)*D + k0 + k];
        }
        for (int x = t; x < GBK*GBN; x += 256) {
            int k = x >> 6, n = x & 63;
            Bs[k][n] = B[(size_t)(k0 + k)*ldb + boff + n0 + n];
        }
        __syncthreads();
        #pragma unroll
        for (int kk = 0; kk < GBK; kk++) {
            float a[4], w[4];
            #pragma unroll
            for (int u = 0; u < 4; u++) a[u] = As[ty*4 + u][kk];
            #pragma unroll
            for (int v = 0; v < 4; v++) w[v] = Bs[kk][tx*4 + v];
            #pragma unroll
            for (int u = 0; u < 4; u++)
                #pragma unroll
                for (int v = 0; v < 4; v++) acc[u][v] += a[u] * w[v];
        }
        __syncthreads();
    }
    #pragma unroll
    for (int u = 0; u < 4; u++)
        #pragma unroll
        for (int v = 0; v < 4; v++)
            C[(size_t)(m0 + ty*4 + u)*D + n0 + tx*4 + v] = alpha * acc[u][v];
}

__device__ __forceinline__ void gemm_nt_body(const float* __restrict__ A,
                                             const float* __restrict__ W,
                                             const float* __restrict__ bias,
                                             float* __restrict__ C, int ldc,
                                             int m0, int n0, float alpha) {
    __shared__ float As[GBM][GBK + 1];
    __shared__ float Ws[GBN][GBK + 1];
    const int t = threadIdx.x;
    const int tx = t & 15, ty = t >> 4;
    float acc[4][4] = {};
    for (int k0 = 0; k0 < D; k0 += GBK) {
        for (int x = t; x < GBM*GBK; x += 256) {
            int m = x >> 4, k = x & 15;
            As[m][k] = A[(size_t)(m0 + m)*D + k0 + k];
        }
        for (int x = t; x < GBN*GBK; x += 256) {
            int n = x >> 4, k = x & 15;
            Ws[n][k] = W[(size_t)(n0 + n)*D + k0 + k];
        }
        __syncthreads();
        #pragma unroll
        for (int kk = 0; kk < GBK; kk++) {
            float a[4], w[4];
            #pragma unroll
            for (int u = 0; u < 4; u++) a[u] = As[ty*4 + u][kk];
            #pragma unroll
            for (int v = 0; v < 4; v++) w[v] = Ws[tx*4 + v][kk];
            #pragma unroll
            for (int u = 0; u < 4; u++)
                #pragma unroll
                for (int v = 0; v < 4; v++) acc[u][v] += a[u] * w[v];
        }
        __syncthreads();
    }
    #pragma unroll
    for (int u = 0; u < 4; u++)
        #pragma unroll
        for (int v = 0; v < 4; v++) {
            int m = m0 + ty*4 + u, n = n0 + tx*4 + v;
            float bb = bias ? bias[n] : 0.f;
            C[(size_t)m*ldc + n] = alpha * (acc[u][v] + bb);
        }
}

// ================= pre1: DD GEMMs {M, WD, WQ, W2V} + setup =================
__global__ void __launch_bounds__(256)
k_pre1(const int* __restrict__ spk,
       const float* __restrict__ Wq1, const float* __restrict__ bq1,
       const float* __restrict__ b_intra,
       const float* __restrict__ Wq2, const float* __restrict__ bq2,
       const float* __restrict__ b_inter,
       const float* __restrict__ W_intra, const float* __restrict__ W_inter,
       const float* __restrict__ Wk2, const float* __restrict__ Wv2) {
    const int blk = blockIdx.x, t = threadIdx.x;
    if (blk < 576) {
        const int z = blk / 144, id = blk % 144;
        const int m0 = (id / 12) * GBM, n0 = (id % 12) * GBN;
        switch (z) {
            case 0: gemm_ab_body(Wq1, W_intra, 2*D, 0, g_M,  m0, n0, SCALE); break;
            case 1: gemm_ab_body(Wq1, W_intra, 2*D, D, g_WD, m0, n0, 1.f);   break;
            case 2: gemm_ab_body(Wq2, W_inter, D,   0, g_WQ, m0, n0, 1.f);   break;
            default: gemm_ab_body(Wk2, Wv2,    D,   0, g_W2V, m0, n0, 1.f);  break;
        }
    } else {
        const int sb = blk - 576;
        if (sb < 8) {
            int i = sb * 256 + t;
            int s = spk[i], r = -1;
            for (int j = i - 1; j >= 0; j--)
                if (spk[j] == s) { r = j; break; }
            g_tmp[i] = r;
        } else if (sb < 200) {
            const int rid = (sb - 8) * 8 + (t >> 5);   // 0..1535
            const int lane = t & 31;
            const int mat = rid >= D;
            const int r = mat ? rid - D : rid;
            const float* W  = mat ? Wq2 : Wq1;
            const float* bv = mat ? b_inter : b_intra;
            float a = 0.f;
            for (int k = lane; k < D; k += 32) a += W[(size_t)r*D + k] * bv[k];
            a = wreduce(a);
            if (lane == 0) {
                if (mat) g_bQ[r] = a + bq2[r];
                else     g_bD[r] = a + bq1[r];
            }
        } else {
            if (t == 0) {
                g_root = 0ULL;
                for (int s = 0; s < NSL; s++) {
                    g_sum1[s] = 0.f; g_sum2[s] = 0.f;
                    g_phi[s] = 0.f;  g_psi[s] = 0.f;
                }
            }
            for (int c = t; c < D; c += 256)
                for (int s = 0; s < NSL; s++) {
                    g_vacc1[s][c] = 0.f; g_vaccV[s][c] = 0.f;
                }
        }
    }
}

// ================= pre2: ND GEMMs {K1, V1, D1, Q2} + MW =================
__global__ void __launch_bounds__(256)
k_pre2(const float* __restrict__ U,
       const float* __restrict__ Wk1, const float* __restrict__ bk1,
       const float* __restrict__ Wv1, const float* __restrict__ bv1,
       const float* __restrict__ Wv2) {
    const int blk = blockIdx.x;
    if (blk < 1536) {
        const int z = blk / 384, id = blk % 384;
        const int m0 = (id / 12) * GBM, n0 = (id % 12) * GBN;
        switch (z) {
            case 0: gemm_nt_body(U, Wk1,  bk1,  g_K1, D, m0, n0, 1.f);   break;
            case 1: gemm_nt_body(U, Wv1,  bv1,  g_V1, D, m0, n0, 1.f);   break;
            case 2: gemm_nt_body(U, g_WD, g_bD, g_D1, D, m0, n0, SCALE); break;
            default: gemm_nt_body(U, g_WQ, g_bQ, g_Q2, D, m0, n0, 1.f);  break;
        }
    } else {
        const int id = blk - 1536;   // 0..143 : MW = M @ Wv2
        const int m0 = (id / 12) * GBM, n0 = (id % 12) * GBN;
        gemm_ab_body(g_M, Wv2, D, 0, g_MW, m0, n0, 1.f);
    }
}

// ================= pre3: post GEMMs {Z2, KM, ZW, KMW} + S1b (lower tri) =================
__global__ void __launch_bounds__(256)
k_pre3(const float* __restrict__ Wk2) {
    const int blk = blockIdx.x;
    if (blk < 1536) {
        const int z = blk / 384, id = blk % 384;
        const int m0 = (id / 12) * GBM, n0 = (id % 12) * GBN;
        switch (z) {
            case 0: gemm_ab_body(g_Q2, Wk2,   D, 0, g_Z2,  m0, n0, SCALE); break;
            case 1: gemm_ab_body(g_K1, g_M,   D, 0, g_KM,  m0, n0, 1.f);   break;
            case 2: gemm_ab_body(g_Q2, g_W2V, D, 0, g_ZW,  m0, n0, SCALE); break;
            default: gemm_ab_body(g_K1, g_MW, D, 0, g_KMW, m0, n0, 1.f);   break;
        }
    } else {
        const int id = blk - 1536;   // 0..1023 : S1b = D1 @ K1^T (N x N)
        const int bm = id / 32, bn = id % 32;
        if (bn > bm) return;         // only j <= i needed
        gemm_nt_body(g_D1, g_K1, (const float*)0, g_S1b, N, bm*GBM, bn*GBN, 1.f);
    }
}

// ================= main recurrence: minimal chain + overlapped bulk =================
__global__ void __launch_bounds__(NT, 1)
k_main(const float* __restrict__ U,
       const float* __restrict__ Wv2, const float* __restrict__ bv2,
       float* __restrict__ Vout) {
    extern __shared__ float sm[];
    float* sWv2  = sm + OFF_WV2;
    float* sY1   = sm + OFF_Y1;
    float* sY2   = sm + OFF_Y2;
    float* sVtN  = sm + OFF_VTN;
    float* sZ2B  = sm + OFF_Z2B;   // [2][D]
    float* sZWB  = sm + OFF_ZWB;   // [2][D]
    int*   sTmpI = (int*)(sm + OFF_TMPI);

    __shared__ float sE1[NWARP], sE2[NWARP];

    const int b = blockIdx.x, t = threadIdx.x;
    const int warp = t >> 5, lane = t & 31;
    const int gw = b * NWARP + warp;   // global warp = global row index

    for (int x = t; x < RPB*D; x += NT)
        sWv2[x] = Wv2[(size_t)(b*RPB)*D + x];
    for (int x = t; x < N; x += NT) sTmpI[x] = g_tmp[x];
    // prime the Z2/ZW smem ring with rows 0 and 1
    for (int c = t; c < D; c += NT) {
        sZ2B[c]     = g_Z2[c];           sZWB[c]     = g_ZW[c];
        sZ2B[D + c] = g_Z2[(size_t)D + c]; sZWB[D + c] = g_ZW[(size_t)D + c];
    }
    __syncthreads();

    unsigned long long nbar = 0;

    for (int i = 0; i <= N; i++) {
        const int tmp  = (i < N)     ? sTmpI[i]     : -1;
        const int tmpn = (i + 1 < N) ? sTmpI[i + 1] : -1;
        const int q = (i + 3) & 3, p = i & 3, pn = (i + 1) & 3, z = (i + 2) & 3;
        const int curb = i & 1, nxtb = curb ^ 1;
        bool hv = false;
        const bool fresh = (tmp >= 0) && (tmp == i - 1);
        const bool pipeN = (i + 1 < N) && (tmpn >= 0) && (tmpn <= i - 1);
        const bool preN  = pipeN && (tmpn <= i - 2);

        // ---- phase head: y-build (the only mandatory L2 round) ----
        if (i > 0) {
            hv = (sTmpI[i-1] >= 0);
            if (hv) {
                float sv1 = 0.f, sv2 = 0.f, pv = 0.f, ps = 0.f;
                if (lane == 0) {
                    sv1 = __ldcg(&g_sum1[q]);
                    sv2 = __ldcg(&g_sum2[q]);
                    pv  = __ldcg(&g_phi[q]);
                    ps  = __ldcg(&g_psi[q]);
                }
                sv1 = __shfl_sync(0xffffffffu, sv1, 0);
                sv2 = __shfl_sync(0xffffffffu, sv2, 0);
                pv  = __shfl_sync(0xffffffffu, pv, 0);
                ps  = __shfl_sync(0xffffffffu, ps, 0);
                const float s1i = 1.0f / sv1, s2i = 1.0f / sv2;
                const float* vpf = Vout + (size_t)(i-2)*D;               // phi row
                const float* vps = Vout + (size_t)((i >= 3) ? (i-3) : 0)*D; // psi row
                for (int c = t; c < D; c += NT) {
                    sY1[c] = __ldcg(&g_vacc1[q][c]) * s1i + bv2[c];
                    sY2[c] = (__ldcg(&g_vaccV[q][c]) + pv*vpf[c] + ps*vps[c]) * s2i;
                }
            } else {
                const float* ur = U + (size_t)(i-1)*D;
                for (int c = t; c < D; c += NT) { sY1[c] = ur[c]; sY2[c] = 0.f; }
            }
        }
        if (t < RPB) {
            g_vacc1[z][b*RPB + t] = 0.f;
            g_vaccV[z][b*RPB + t] = 0.f;
        }
        if (b == 3 && t == 0) {
            g_sum1[z] = 0.f; g_sum2[z] = 0.f; g_phi[z] = 0.f; g_psi[z] = 0.f;
        }
        __syncthreads();

        // ---- on-chain compute (smem dots only, except fresh path) ----
        if (fresh) {
            // intra scores via implicit V[i-1] = y1 + Wv2*y2 (KM/KMW rows L1-hot)
            float s1v = (lane == 0 && gw <= i) ? __ldg(&g_S1b[(size_t)i*N + gw]) : 0.f;
            float e = 0.f;
            if (gw <= i) {
                float a = wdot(g_KM + (size_t)gw*D, sY1, lane);
                if (hv) a += wdot(g_KMW + (size_t)gw*D, sY2, lane);
                a = wreduce(a);
                e = __expf(a + s1v);
            }
            if (lane == 0) sE1[warp] = e;
        }
        // phi(i): deferred inter row i-1 (smem ring holds Z2/ZW row i)
        if (i < N && tmp >= 0 && b == 1 && warp == 15) {
            float a = wdot(sZ2B + curb*D, sY1, lane);
            if (hv) a += wdot(sZWB + curb*D, sY2, lane);
            a = wreduce(a);
            if (lane == 0) {
                const float e = __expf(a);
                atomicAdd(&g_sum2[p], e);
                g_phi[p] = e;
            }
        }
        // psi(i+1): deferred inter row i-1 for step i+1 (Z2/ZW row i+1 in ring)
        if (i + 1 < N && b == 2 && warp == 15) {
            if (tmpn >= 0 && tmpn <= i - 1) {
                float a = wdot(sZ2B + nxtb*D, sY1, lane);
                if (hv) a += wdot(sZWB + nxtb*D, sY2, lane);
                a = wreduce(a);
                if (lane == 0) {
                    const float e = __expf(a);
                    atomicAdd(&g_sum2[pn], e);
                    g_psi[pn] = e;
                }
            } else if (lane == 0) {
                g_psi[pn] = 0.f;
            }
        }
        // finalize V[i-1] (block-owned rows)
        if (i > 0 && warp < RPB) {
            const int r = b*RPB + warp;
            float a = 0.f;
            if (hv) a = wreduce(wdot(sWv2 + warp*D, sY2, lane));
            if (lane == 0) Vout[(size_t)(i-1)*D + r] = sY1[r] + a;
        }
        if (i == N) break;
        __syncthreads();

        // ---- on-chain accumulation: FRESH steps only (~6%) ----
        if (fresh) {
            if (warp == 0) {
                float v1 = (lane < NWARP) ? sE1[lane] : 0.f;
                v1 = wreduce(v1);
                if (lane == 0) atomicAdd(&g_sum1[p], v1);
            }
            if (t < 192 && b*NWARP <= i) {
                float4 a = make_float4(0.f, 0.f, 0.f, 0.f);
                #pragma unroll
                for (int w = 0; w < NWARP; w++) {
                    const float e = sE1[w];
                    const float4 v = ((const float4*)(g_V1 + (size_t)(b*NWARP + w)*D))[t];
                    a.x += e*v.x; a.y += e*v.y; a.z += e*v.z; a.w += e*v.w;
                }
                float* dst = &g_vacc1[p][t*4];
                atomicAdd(dst+0, a.x); atomicAdd(dst+1, a.y);
                atomicAdd(dst+2, a.z); atomicAdd(dst+3, a.w);
            }
        }

        bar_arrive();

        // ================= OVERLAP (between arrive and wait) =================
        // stage loads
        if (preN) {
            const float* vtn = Vout + (size_t)tmpn*D;    // row <= i-2: sealed
            for (int c = t; c < D; c += NT) sVtN[c] = vtn[c];
        }
        if (i + 2 < N) {  // prefetch Z2/ZW rows i+2 into the ring slot [curb]
            const float* z2r = g_Z2 + (size_t)(i+2)*D;
            const float* zwr = g_ZW + (size_t)(i+2)*D;
            for (int c = t; c < D; c += NT) {
                sZ2B[curb*D + c] = z2r[c];
                sZWB[curb*D + c] = zwr[c];
            }
        }
        __syncthreads();

        if (pipeN) {
            // intra scores for step i+1 (all rows; V1/KM/S1b static)
            float s1v = (lane == 0 && gw <= i + 1) ? __ldg(&g_S1b[(size_t)(i+1)*N + gw]) : 0.f;
            float e = 0.f;
            if (gw <= i + 1) {
                float a;
                if (preN) {
                    a = wdot(g_KM + (size_t)gw*D, sVtN, lane);
                } else {  // semi: v_tmp = V[i-1] implicit
                    a = wdot(g_KM + (size_t)gw*D, sY1, lane);
                    if (hv) a += wdot(g_KMW + (size_t)gw*D, sY2, lane);
                }
                a = wreduce(a);
                e = __expf(a + s1v);
            }
            if (lane == 0) sE1[warp] = e;
            // inter direct rows j <= i-2 (rows i-1, i deferred via psi/phi)
            float e2 = 0.f;
            const int j = tmpn + gw;
            if (j <= i - 2) {
                float a = wreduce(wdot(Vout + (size_t)j*D, sZ2B + nxtb*D, lane));
                e2 = __expf(a);
            }
            if (lane == 0) sE2[warp] = e2;
        }
        __syncthreads();

        if (pipeN) {
            if (warp == 0) {
                float v1 = (lane < NWARP) ? sE1[lane] : 0.f;
                float v2 = (lane < NWARP) ? sE2[lane] : 0.f;
                v1 = wreduce(v1); v2 = wreduce(v2);
                if (lane == 0) {
                    if (v1 != 0.f) atomicAdd(&g_sum1[pn], v1);
                    if (v2 != 0.f) atomicAdd(&g_sum2[pn], v2);
                }
            }
            if (t < 192) {
                if (b*NWARP <= i + 1) {
                    float4 a = make_float4(0.f, 0.f, 0.f, 0.f);
                    #pragma unroll
                    for (int w = 0; w < NWARP; w++) {
                        const float e = sE1[w];
                        const float4 v = ((const float4*)(g_V1 + (size_t)(b*NWARP + w)*D))[t];
                        a.x += e*v.x; a.y += e*v.y; a.z += e*v.z; a.w += e*v.w;
                    }
                    float* dst = &g_vacc1[pn][t*4];
                    atomicAdd(dst+0, a.x); atomicAdd(dst+1, a.y);
                    atomicAdd(dst+2, a.z); atomicAdd(dst+3, a.w);
                }
            } else if (t >= 256 && t < 448) {
                const int c4 = t - 256;
                const int base2 = tmpn + b*NWARP;
                if (base2 <= i - 2) {
                    float4 a = make_float4(0.f, 0.f, 0.f, 0.f);
                    #pragma unroll
                    for (int w = 0; w < NWARP; w++) {
                        const float e = sE2[w];
                        int j = base2 + w; if (j > N - 1) j = N - 1;   // e==0 there
                        const float4 v = ((const float4*)(Vout + (size_t)j*D))[c4];
                        a.x += e*v.x; a.y += e*v.y; a.z += e*v.z; a.w += e*v.w;
                    }
                    float* dst = &g_vaccV[pn][c4*4];
                    atomicAdd(dst+0, a.x); atomicAdd(dst+1, a.y);
                    atomicAdd(dst+2, a.z); atomicAdd(dst+3, a.w);
                }
            }
        }
        bar_wait(nbar);
    }
}

// ---------------- launch : k_main is launch #4 ----------------
extern "C" void kernel_launch(void* const* d_in, const int* in_sizes, int n_in,
                              void* d_out, int out_size) {
    const float* U       = (const float*)d_in[0];
    const int*   spk     = (const int*)  d_in[1];
    const float* W_intra = (const float*)d_in[2];
    const float* b_intra = (const float*)d_in[3];
    const float* W_inter = (const float*)d_in[4];
    const float* b_inter = (const float*)d_in[5];
    const float* Wq1 = (const float*)d_in[6];  const float* bq1 = (const float*)d_in[7];
    const float* Wk1 = (const float*)d_in[8];  const float* bk1 = (const float*)d_in[9];
    const float* Wv1 = (const float*)d_in[10]; const float* bv1 = (const float*)d_in[11];
    const float* Wq2 = (const float*)d_in[12]; const float* bq2 = (const float*)d_in[13];
    const float* Wk2 = (const float*)d_in[14]; const float* bk2 = (const float*)d_in[15];
    const float* Wv2 = (const float*)d_in[16]; const float* bv2 = (const float*)d_in[17];
    float* Vout = (float*)d_out;
    (void)in_sizes; (void)n_in; (void)out_size; (void)bk2;

    cudaFuncSetAttribute(k_main, cudaFuncAttributeMaxDynamicSharedMemorySize, SMEM_BYTES);

    k_pre1<<<777, 256>>>(spk, Wq1, bq1, b_intra, Wq2, bq2, b_inter,
                         W_intra, W_inter, Wk2, Wv2);                 // 1
    k_pre2<<<1680, 256>>>(U, Wk1, bk1, Wv1, bv1, Wv2);                // 2
    k_pre3<<<2560, 256>>>(Wk2);                                       // 3
    k_main<<<NB, NT, SMEM_BYTES>>>(U, Wv2, bv2, Vout);                // 4
}

// round 13
// speedup vs baseline: 1.7684x; 1.0626x over previous
#include <cuda_runtime.h>
#include <math.h>

#define N 2048
#define D 768
#define SCALE 0.036084391824351615f  /* 1/sqrt(768) */

#define NB 128
#define NT 512
#define NWARP (NT/32)     /* 16 */
#define RPB (D / NB)      /* 6 rows per block */
#define NSL 4             /* quad-buffered accumulators */

/* k_main dynamic smem layout (float slots) */
#define OFF_WV2   0
#define OFF_Y1    (RPB*D)
#define OFF_Y2    (RPB*D + D)
#define OFF_VTN   (RPB*D + 2*D)
#define OFF_Z2B   (RPB*D + 3*D)            /* 2 rows */
#define OFF_ZWB   (RPB*D + 5*D)            /* 2 rows */
#define OFF_TMPI  (RPB*D + 7*D)
#define SMEM_FLOATS (RPB*D + 7*D + N)
#define SMEM_BYTES  (SMEM_FLOATS * 4)

// ---------------- device globals ----------------
__device__ float g_K1[N*D];
__device__ float g_V1[N*D];
__device__ float g_D1[N*D];            // scale*(U@WD^T + bD)
__device__ float g_Q2[N*D];
__device__ float g_Z2[N*D];            // scale*(Q2@Wk2)
__device__ float g_KM[N*D];            // K1 @ M
__device__ float g_ZW[N*D];            // Z2 @ Wv2
__device__ float g_KMW[N*D];           // KM @ Wv2
__device__ float g_S1b[(size_t)N*N];   // D1 @ K1^T (lower tri used)
__device__ float g_M [D*D];            // scale*(Wq1 @ W_intra[:, :D])
__device__ float g_WD[D*D];
__device__ float g_WQ[D*D];
__device__ float g_W2V[D*D];           // Wk2 @ Wv2
__device__ float g_MW[D*D];            // M @ Wv2
__device__ float g_bD[D];
__device__ float g_bQ[D];
__device__ float g_vacc1[NSL][D];
__device__ float g_vaccV[NSL][D];
__device__ float g_sum1[NSL];
__device__ float g_sum2[NSL];
__device__ float g_phi[NSL];           // deferred inter row s-1
__device__ float g_psi[NSL];           // deferred inter row s-2
__device__ int   g_tmp[N];
__device__ unsigned long long g_root;

// ---------------- helpers ----------------
__device__ __forceinline__ float wreduce(float a) {
    #pragma unroll
    for (int o = 16; o; o >>= 1) a += __shfl_xor_sync(0xffffffffu, a, o);
    return a;
}

__device__ __forceinline__ float wdot(const float* __restrict__ a,
                                      const float* __restrict__ b, int lane) {
    const float4* A = (const float4*)a;
    const float4* B = (const float4*)b;
    float s = 0.f;
    #pragma unroll
    for (int u = 0; u < 6; u++) {
        float4 x = A[lane + 32*u], y = B[lane + 32*u];
        s += x.x*y.x + x.y*y.y + x.z*y.z + x.w*y.w;
    }
    return s;
}

// split-phase fence-free grid barrier
__device__ __forceinline__ void bar_arrive() {
    __syncthreads();
    if (threadIdx.x == 0) {
        unsigned long long one = 1ULL;
        asm volatile("red.release.gpu.add.u64 [%0], %1;"
                     :: "l"(&g_root), "l"(one) : "memory");
    }
}
__device__ __forceinline__ void bar_wait(unsigned long long& nbar) {
    if (threadIdx.x == 0) {
        const unsigned long long tgt = (nbar + 1) * (unsigned long long)NB;
        unsigned long long v;
        do {
            asm volatile("ld.acquire.gpu.u64 %0, [%1];"
                         : "=l"(v) : "l"(&g_root) : "memory");
        } while (v < tgt);
    }
    nbar++;
    __syncthreads();
}

// ================= GEMM tile bodies =================
#define GBM 64
#define GBN 64
#define GBK 16

__device__ __forceinline__ void gemm_ab_body(const float* __restrict__ A,
                                             const float* __restrict__ B,
                                             int ldb, int boff,
                                             float* __restrict__ C,
                                             int m0, int n0, float alpha) {
    __shared__ float As[GBM][GBK + 1];
    __shared__ float Bs[GBK][GBN];
    const int t = threadIdx.x;
    const int tx = t & 15, ty = t >> 4;
    float acc[4][4] = {};
    for (int k0 = 0; k0 < D; k0 += GBK) {
        for (int x = t; x < GBM*GBK; x += 256) {
            int m = x >> 4, k = x & 15;
            As[m][k] = A[(size_t)(m0 + m)*D + k0 + k];
        }
        for (int x = t; x < GBK*GBN; x += 256) {
            int k = x >> 6, n = x & 63;
            Bs[k][n] = B[(size_t)(k0 + k)*ldb + boff + n0 + n];
        }
        __syncthreads();
        #pragma unroll
        for (int kk = 0; kk < GBK; kk++) {
            float a[4], w[4];
            #pragma unroll
            for (int u = 0; u < 4; u++) a[u] = As[ty*4 + u][kk];
            #pragma unroll
            for (int v = 0; v < 4; v++) w[v] = Bs[kk][tx*4 + v];
            #pragma unroll
            for (int u = 0; u < 4; u++)
                #pragma unroll
                for (int v = 0; v < 4; v++) acc[u][v] += a[u] * w[v];
        }
        __syncthreads();
    }
    #pragma unroll
    for (int u = 0; u < 4; u++)
        #pragma unroll
        for (int v = 0; v < 4; v++)
            C[(size_t)(m0 + ty*4 + u)*D + n0 + tx*4 + v] = alpha * acc[u][v];
}

__device__ __forceinline__ void gemm_nt_body(const float* __restrict__ A,
                                             const float* __restrict__ W,
                                             const float* __restrict__ bias,
                                             float* __restrict__ C, int ldc,
                                             int m0, int n0, float alpha) {
    __shared__ float As[GBM][GBK + 1];
    __shared__ float Ws[GBN][GBK + 1];
    const int t = threadIdx.x;
    const int tx = t & 15, ty = t >> 4;
    float acc[4][4] = {};
    for (int k0 = 0; k0 < D; k0 += GBK) {
        for (int x = t; x < GBM*GBK; x += 256) {
            int m = x >> 4, k = x & 15;
            As[m][k] = A[(size_t)(m0 + m)*D + k0 + k];
        }
        for (int x = t; x < GBN*GBK; x += 256) {
            int n = x >> 4, k = x & 15;
            Ws[n][k] = W[(size_t)(n0 + n)*D + k0 + k];
        }
        __syncthreads();
        #pragma unroll
        for (int kk = 0; kk < GBK; kk++) {
            float a[4], w[4];
            #pragma unroll
            for (int u = 0; u < 4; u++) a[u] = As[ty*4 + u][kk];
            #pragma unroll
            for (int v = 0; v < 4; v++) w[v] = Ws[tx*4 + v][kk];
            #pragma unroll
            for (int u = 0; u < 4; u++)
                #pragma unroll
                for (int v = 0; v < 4; v++) acc[u][v] += a[u] * w[v];
        }
        __syncthreads();
    }
    #pragma unroll
    for (int u = 0; u < 4; u++)
        #pragma unroll
        for (int v = 0; v < 4; v++) {
            int m = m0 + ty*4 + u, n = n0 + tx*4 + v;
            float bb = bias ? bias[n] : 0.f;
            C[(size_t)m*ldc + n] = alpha * (acc[u][v] + bb);
        }
}

// ================= pre1: DD GEMMs {M, WD, WQ, W2V} + setup =================
__global__ void __launch_bounds__(256)
k_pre1(const int* __restrict__ spk,
       const float* __restrict__ Wq1, const float* __restrict__ bq1,
       const float* __restrict__ b_intra,
       const float* __restrict__ Wq2, const float* __restrict__ bq2,
       const float* __restrict__ b_inter,
       const float* __restrict__ W_intra, const float* __restrict__ W_inter,
       const float* __restrict__ Wk2, const float* __restrict__ Wv2) {
    const int blk = blockIdx.x, t = threadIdx.x;
    if (blk < 576) {
        const int z = blk / 144, id = blk % 144;
        const int m0 = (id / 12) * GBM, n0 = (id % 12) * GBN;
        switch (z) {
            case 0: gemm_ab_body(Wq1, W_intra, 2*D, 0, g_M,  m0, n0, SCALE); break;
            case 1: gemm_ab_body(Wq1, W_intra, 2*D, D, g_WD, m0, n0, 1.f);   break;
            case 2: gemm_ab_body(Wq2, W_inter, D,   0, g_WQ, m0, n0, 1.f);   break;
            default: gemm_ab_body(Wk2, Wv2,    D,   0, g_W2V, m0, n0, 1.f);  break;
        }
    } else {
        const int sb = blk - 576;
        if (sb < 8) {
            int i = sb * 256 + t;
            int s = spk[i], r = -1;
            for (int j = i - 1; j >= 0; j--)
                if (spk[j] == s) { r = j; break; }
            g_tmp[i] = r;
        } else if (sb < 200) {
            const int rid = (sb - 8) * 8 + (t >> 5);   // 0..1535
            const int lane = t & 31;
            const int mat = rid >= D;
            const int r = mat ? rid - D : rid;
            const float* W  = mat ? Wq2 : Wq1;
            const float* bv = mat ? b_inter : b_intra;
            float a = 0.f;
            for (int k = lane; k < D; k += 32) a += W[(size_t)r*D + k] * bv[k];
            a = wreduce(a);
            if (lane == 0) {
                if (mat) g_bQ[r] = a + bq2[r];
                else     g_bD[r] = a + bq1[r];
            }
        } else {
            if (t == 0) {
                g_root = 0ULL;
                for (int s = 0; s < NSL; s++) {
                    g_sum1[s] = 0.f; g_sum2[s] = 0.f;
                    g_phi[s] = 0.f;  g_psi[s] = 0.f;
                }
            }
            for (int c = t; c < D; c += 256)
                for (int s = 0; s < NSL; s++) {
                    g_vacc1[s][c] = 0.f; g_vaccV[s][c] = 0.f;
                }
        }
    }
}

// ================= pre2: ND GEMMs {K1, V1, D1, Q2} + MW =================
__global__ void __launch_bounds__(256)
k_pre2(const float* __restrict__ U,
       const float* __restrict__ Wk1, const float* __restrict__ bk1,
       const float* __restrict__ Wv1, const float* __restrict__ bv1,
       const float* __restrict__ Wv2) {
    const int blk = blockIdx.x;
    if (blk < 1536) {
        const int z = blk / 384, id = blk % 384;
        const int m0 = (id / 12) * GBM, n0 = (id % 12) * GBN;
        switch (z) {
            case 0: gemm_nt_body(U, Wk1,  bk1,  g_K1, D, m0, n0, 1.f);   break;
            case 1: gemm_nt_body(U, Wv1,  bv1,  g_V1, D, m0, n0, 1.f);   break;
            case 2: gemm_nt_body(U, g_WD, g_bD, g_D1, D, m0, n0, SCALE); break;
            default: gemm_nt_body(U, g_WQ, g_bQ, g_Q2, D, m0, n0, 1.f);  break;
        }
    } else {
        const int id = blk - 1536;   // 0..143 : MW = M @ Wv2
        const int m0 = (id / 12) * GBM, n0 = (id % 12) * GBN;
        gemm_ab_body(g_M, Wv2, D, 0, g_MW, m0, n0, 1.f);
    }
}

// ================= pre3: post GEMMs {Z2, KM, ZW, KMW} + S1b (lower tri) =================
__global__ void __launch_bounds__(256)
k_pre3(const float* __restrict__ Wk2) {
    const int blk = blockIdx.x;
    if (blk < 1536) {
        const int z = blk / 384, id = blk % 384;
        const int m0 = (id / 12) * GBM, n0 = (id % 12) * GBN;
        switch (z) {
            case 0: gemm_ab_body(g_Q2, Wk2,   D, 0, g_Z2,  m0, n0, SCALE); break;
            case 1: gemm_ab_body(g_K1, g_M,   D, 0, g_KM,  m0, n0, 1.f);   break;
            case 2: gemm_ab_body(g_Q2, g_W2V, D, 0, g_ZW,  m0, n0, SCALE); break;
            default: gemm_ab_body(g_K1, g_MW, D, 0, g_KMW, m0, n0, 1.f);   break;
        }
    } else {
        const int id = blk - 1536;   // 0..1023 : S1b = D1 @ K1^T (N x N)
        const int bm = id / 32, bn = id % 32;
        if (bn > bm) return;         // only j <= i needed
        gemm_nt_body(g_D1, g_K1, (const float*)0, g_S1b, N, bm*GBM, bn*GBN, 1.f);
    }
}

// ================= main recurrence: minimal chain + overlapped bulk =================
__global__ void __launch_bounds__(NT, 1)
k_main(const float* __restrict__ U,
       const float* __restrict__ Wv2, const float* __restrict__ bv2,
       float* __restrict__ Vout) {
    extern __shared__ float sm[];
    float* sWv2  = sm + OFF_WV2;
    float* sY1   = sm + OFF_Y1;
    float* sY2   = sm + OFF_Y2;
    float* sVtN  = sm + OFF_VTN;
    float* sZ2B  = sm + OFF_Z2B;   // [2][D]
    float* sZWB  = sm + OFF_ZWB;   // [2][D]
    int*   sTmpI = (int*)(sm + OFF_TMPI);

    __shared__ float sE1[NWARP], sE2[NWARP];

    const int b = blockIdx.x, t = threadIdx.x;
    const int warp = t >> 5, lane = t & 31;
    const int gw = b * NWARP + warp;   // global warp = global row index

    for (int x = t; x < RPB*D; x += NT)
        sWv2[x] = Wv2[(size_t)(b*RPB)*D + x];
    for (int x = t; x < N; x += NT) sTmpI[x] = g_tmp[x];
    // prime the Z2/ZW smem ring with rows 0 and 1
    for (int c = t; c < D; c += NT) {
        sZ2B[c]     = g_Z2[c];           sZWB[c]     = g_ZW[c];
        sZ2B[D + c] = g_Z2[(size_t)D + c]; sZWB[D + c] = g_ZW[(size_t)D + c];
    }
    __syncthreads();

    unsigned long long nbar = 0;

    for (int i = 0; i <= N; i++) {
        const int tmp  = (i < N)     ? sTmpI[i]     : -1;
        const int tmpn = (i + 1 < N) ? sTmpI[i + 1] : -1;
        const int q = (i + 3) & 3, p = i & 3, pn = (i + 1) & 3, z = (i + 2) & 3;
        const int curb = i & 1, nxtb = curb ^ 1;
        bool hv = false;
        const bool fresh = (tmp >= 0) && (tmp == i - 1);
        const bool pipeN = (i + 1 < N) && (tmpn >= 0) && (tmpn <= i - 1);
        const bool preN  = pipeN && (tmpn <= i - 2);

        // ---- phase head: y-build (the only mandatory L2 round) ----
        if (i > 0) {
            hv = (sTmpI[i-1] >= 0);
            if (hv) {
                float sv1 = 0.f, sv2 = 0.f, pv = 0.f, ps = 0.f;
                if (lane == 0) {
                    sv1 = __ldcg(&g_sum1[q]);
                    sv2 = __ldcg(&g_sum2[q]);
                    pv  = __ldcg(&g_phi[q]);
                    ps  = __ldcg(&g_psi[q]);
                }
                sv1 = __shfl_sync(0xffffffffu, sv1, 0);
                sv2 = __shfl_sync(0xffffffffu, sv2, 0);
                pv  = __shfl_sync(0xffffffffu, pv, 0);
                ps  = __shfl_sync(0xffffffffu, ps, 0);
                const float s1i = 1.0f / sv1, s2i = 1.0f / sv2;
                const float* vpf = Vout + (size_t)(i-2)*D;               // phi row
                const float* vps = Vout + (size_t)((i >= 3) ? (i-3) : 0)*D; // psi row
                for (int c = t; c < D; c += NT) {
                    sY1[c] = __ldcg(&g_vacc1[q][c]) * s1i + bv2[c];
                    sY2[c] = (__ldcg(&g_vaccV[q][c]) + pv*vpf[c] + ps*vps[c]) * s2i;
                }
            } else {
                const float* ur = U + (size_t)(i-1)*D;
                for (int c = t; c < D; c += NT) { sY1[c] = ur[c]; sY2[c] = 0.f; }
            }
        }
        if (t < RPB) {
            g_vacc1[z][b*RPB + t] = 0.f;
            g_vaccV[z][b*RPB + t] = 0.f;
        }
        if (b == 3 && t == 0) {
            g_sum1[z] = 0.f; g_sum2[z] = 0.f; g_phi[z] = 0.f; g_psi[z] = 0.f;
        }
        __syncthreads();

        // ---- on-chain compute (smem dots only, except fresh path) ----
        if (fresh) {
            // intra scores via implicit V[i-1] = y1 + Wv2*y2 (KM/KMW rows L1-hot)
            float s1v = (lane == 0 && gw <= i) ? __ldg(&g_S1b[(size_t)i*N + gw]) : 0.f;
            float e = 0.f;
            if (gw <= i) {
                float a = wdot(g_KM + (size_t)gw*D, sY1, lane);
                if (hv) a += wdot(g_KMW + (size_t)gw*D, sY2, lane);
                a = wreduce(a);
                e = __expf(a + s1v);
            }
            if (lane == 0) sE1[warp] = e;
        }
        // phi(i): deferred inter row i-1 (smem ring holds Z2/ZW row i)
        if (i < N && tmp >= 0 && b == 1 && warp == 15) {
            float a = wdot(sZ2B + curb*D, sY1, lane);
            if (hv) a += wdot(sZWB + curb*D, sY2, lane);
            a = wreduce(a);
            if (lane == 0) {
                const float e = __expf(a);
                atomicAdd(&g_sum2[p], e);
                g_phi[p] = e;
            }
        }
        // psi(i+1): deferred inter row i-1 for step i+1 (Z2/ZW row i+1 in ring)
        if (i + 1 < N && b == 2 && warp == 15) {
            if (tmpn >= 0 && tmpn <= i - 1) {
                float a = wdot(sZ2B + nxtb*D, sY1, lane);
                if (hv) a += wdot(sZWB + nxtb*D, sY2, lane);
                a = wreduce(a);
                if (lane == 0) {
                    const float e = __expf(a);
                    atomicAdd(&g_sum2[pn], e);
                    g_psi[pn] = e;
                }
            } else if (lane == 0) {
                g_psi[pn] = 0.f;
            }
        }
        // finalize V[i-1] (block-owned rows)
        if (i > 0 && warp < RPB) {
            const int r = b*RPB + warp;
            float a = 0.f;
            if (hv) a = wreduce(wdot(sWv2 + warp*D, sY2, lane));
            if (lane == 0) Vout[(size_t)(i-1)*D + r] = sY1[r] + a;
        }
        if (i == N) break;
        __syncthreads();

        // ---- on-chain accumulation: FRESH steps only (~6%) ----
        if (fresh) {
            if (warp == 0) {
                float v1 = (lane < NWARP) ? sE1[lane] : 0.f;
                v1 = wreduce(v1);
                if (lane == 0) atomicAdd(&g_sum1[p], v1);
            }
            if (t < 192 && b*NWARP <= i) {
                float4 a = make_float4(0.f, 0.f, 0.f, 0.f);
                #pragma unroll
                for (int w = 0; w < NWARP; w++) {
                    const float e = sE1[w];
                    const float4 v = ((const float4*)(g_V1 + (size_t)(b*NWARP + w)*D))[t];
                    a.x += e*v.x; a.y += e*v.y; a.z += e*v.z; a.w += e*v.w;
                }
                float* dst = &g_vacc1[p][t*4];
                atomicAdd(dst+0, a.x); atomicAdd(dst+1, a.y);
                atomicAdd(dst+2, a.z); atomicAdd(dst+3, a.w);
            }
        }

        bar_arrive();

        // ================= OVERLAP (between arrive and wait) =================
        // stage loads
        if (preN) {
            const float* vtn = Vout + (size_t)tmpn*D;    // row <= i-2: sealed
            for (int c = t; c < D; c += NT) sVtN[c] = vtn[c];
        }
        if (i + 2 < N) {  // prefetch Z2/ZW rows i+2 into the ring slot [curb]
            const float* z2r = g_Z2 + (size_t)(i+2)*D;
            const float* zwr = g_ZW + (size_t)(i+2)*D;
            for (int c = t; c < D; c += NT) {
                sZ2B[curb*D + c] = z2r[c];
                sZWB[curb*D + c] = zwr[c];
            }
        }
        __syncthreads();

        if (pipeN) {
            // intra scores for step i+1 (all rows; V1/KM/S1b static)
            float s1v = (lane == 0 && gw <= i + 1) ? __ldg(&g_S1b[(size_t)(i+1)*N + gw]) : 0.f;
            float e = 0.f;
            if (gw <= i + 1) {
                float a;
                if (preN) {
                    a = wdot(g_KM + (size_t)gw*D, sVtN, lane);
                } else {  // semi: v_tmp = V[i-1] implicit
                    a = wdot(g_KM + (size_t)gw*D, sY1, lane);
                    if (hv) a += wdot(g_KMW + (size_t)gw*D, sY2, lane);
                }
                a = wreduce(a);
                e = __expf(a + s1v);
            }
            if (lane == 0) sE1[warp] = e;
            // inter direct rows j <= i-2 (rows i-1, i deferred via psi/phi)
            float e2 = 0.f;
            const int j = tmpn + gw;
            if (j <= i - 2) {
                float a = wreduce(wdot(Vout + (size_t)j*D, sZ2B + nxtb*D, lane));
                e2 = __expf(a);
            }
            if (lane == 0) sE2[warp] = e2;
        }
        __syncthreads();

        if (pipeN) {
            if (warp == 0) {
                float v1 = (lane < NWARP) ? sE1[lane] : 0.f;
                float v2 = (lane < NWARP) ? sE2[lane] : 0.f;
                v1 = wreduce(v1); v2 = wreduce(v2);
                if (lane == 0) {
                    if (v1 != 0.f) atomicAdd(&g_sum1[pn], v1);
                    if (v2 != 0.f) atomicAdd(&g_sum2[pn], v2);
                }
            }
            if (t < 192) {
                if (b*NWARP <= i + 1) {
                    float4 a = make_float4(0.f, 0.f, 0.f, 0.f);
                    #pragma unroll
                    for (int w = 0; w < NWARP; w++) {
                        const float e = sE1[w];
                        const float4 v = ((const float4*)(g_V1 + (size_t)(b*NWARP + w)*D))[t];
                        a.x += e*v.x; a.y += e*v.y; a.z += e*v.z; a.w += e*v.w;
                    }
                    float* dst = &g_vacc1[pn][t*4];
                    atomicAdd(dst+0, a.x); atomicAdd(dst+1, a.y);
                    atomicAdd(dst+2, a.z); atomicAdd(dst+3, a.w);
                }
            } else if (t >= 256 && t < 448) {
                const int c4 = t - 256;
                const int base2 = tmpn + b*NWARP;
                if (base2 <= i - 2) {
                    float4 a = make_float4(0.f, 0.f, 0.f, 0.f);
                    #pragma unroll
                    for (int w = 0; w < NWARP; w++) {
                        const float e = sE2[w];
                        int j = base2 + w; if (j > N - 1) j = N - 1;   // e==0 there
                        const float4 v = ((const float4*)(Vout + (size_t)j*D))[c4];
                        a.x += e*v.x; a.y += e*v.y; a.z += e*v.z; a.w += e*v.w;
                    }
                    float* dst = &g_vaccV[pn][c4*4];
                    atomicAdd(dst+0, a.x); atomicAdd(dst+1, a.y);
                    atomicAdd(dst+2, a.z); atomicAdd(dst+3, a.w);
                }
            }
        }
        bar_wait(nbar);
    }
}

// ---------------- launch : k_main is launch #4 ----------------
extern "C" void kernel_launch(void* const* d_in, const int* in_sizes, int n_in,
                              void* d_out, int out_size) {
    const float* U       = (const float*)d_in[0];
    const int*   spk     = (const int*)  d_in[1];
    const float* W_intra = (const float*)d_in[2];
    const float* b_intra = (const float*)d_in[3];
    const float* W_inter = (const float*)d_in[4];
    const float* b_inter = (const float*)d_in[5];
    const float* Wq1 = (const float*)d_in[6];  const float* bq1 = (const float*)d_in[7];
    const float* Wk1 = (const float*)d_in[8];  const float* bk1 = (const float*)d_in[9];
    const float* Wv1 = (const float*)d_in[10]; const float* bv1 = (const float*)d_in[11];
    const float* Wq2 = (const float*)d_in[12]; const float* bq2 = (const float*)d_in[13];
    const float* Wk2 = (const float*)d_in[14]; const float* bk2 = (const float*)d_in[15];
    const float* Wv2 = (const float*)d_in[16]; const float* bv2 = (const float*)d_in[17];
    float* Vout = (float*)d_out;
    (void)in_sizes; (void)n_in; (void)out_size; (void)bk2;

    cudaFuncSetAttribute(k_main, cudaFuncAttributeMaxDynamicSharedMemorySize, SMEM_BYTES);

    k_pre1<<<777, 256>>>(spk, Wq1, bq1, b_intra, Wq2, bq2, b_inter,
                         W_intra, W_inter, Wk2, Wv2);                 // 1
    k_pre2<<<1680, 256>>>(U, Wk1, bk1, Wv1, bv1, Wv2);                // 2
    k_pre3<<<2560, 256>>>(Wk2);                                       // 3
    k_main<<<NB, NT, SMEM_BYTES>>>(U, Wv2, bv2, Vout);                // 4
}